// round 10
// baseline (speedup 1.0000x reference)
#include <cuda_runtime.h>
#include <cstdint>
#include <math.h>

#define Bz 8
#define Lq 2048
#define Sk 1024
#define DM 1024
#define DLLM 4096
#define NH 16
#define DK 64
#define DHK 1024

// Scratch (allocation-free rule: __device__ globals)
__device__ float g_Q[(size_t)Bz * Lq * DHK];    // 64 MB
__device__ float g_K[(size_t)Bz * Sk * DHK];    // 32 MB
__device__ float g_V[(size_t)Bz * Sk * DHK];    // 32 MB
__device__ float g_C[(size_t)Bz * Lq * DHK];    // 64 MB (perm-rounded target, then attn out)
__device__ float g_WT[(size_t)DLLM * DHK];      // 16 MB (transposed+rounded+K-permuted weight)
__device__ float g_Sr[(size_t)Bz * Sk * DLLM];  // 128 MB (perm-rounded source)

// ===========================================================================
// Helpers
// ===========================================================================
__device__ __forceinline__ uint32_t smem_u32(const void* p) {
    uint32_t a;
    asm("{ .reg .u64 t; cvta.to.shared.u64 t, %1; cvt.u32.u64 %0, t; }" : "=r"(a) : "l"(p));
    return a;
}
__device__ __forceinline__ void cp16(uint32_t dst, const void* src) {
    asm volatile("cp.async.cg.shared.global [%0], [%1], 16;" :: "r"(dst), "l"(src));
}
#define CP_COMMIT() asm volatile("cp.async.commit_group;" ::: "memory")
#define CP_WAIT0()  asm volatile("cp.async.wait_group 0;" ::: "memory")

__device__ __forceinline__ float rnd_tf32(float x) {
    uint32_t r;
    asm("cvt.rna.tf32.f32 %0, %1;" : "=r"(r) : "f"(x));
    return __uint_as_float(r);
}
// K-permutation within groups of 8: pos of original index j is p(j).
// Layout order becomes [0,4,1,5,2,6,3,7] so (k, k+4) pairs are adjacent.
__device__ __forceinline__ int kperm(int j) { return (j < 4) ? 2 * j : 2 * j - 7; }

__device__ __forceinline__ void mma_tf32(float c[4], const uint32_t a[4], const uint32_t b[2]) {
    asm volatile(
        "mma.sync.aligned.m16n8k8.row.col.f32.tf32.tf32.f32 "
        "{%0,%1,%2,%3}, {%4,%5,%6,%7}, {%8,%9}, {%0,%1,%2,%3};"
        : "+f"(c[0]), "+f"(c[1]), "+f"(c[2]), "+f"(c[3])
        : "r"(a[0]), "r"(a[1]), "r"(a[2]), "r"(a[3]), "r"(b[0]), "r"(b[1]));
}

// ===========================================================================
// Elementwise tf32 round + K-pair permutation (row stride divisible by 8,
// so flat_index & 7 == k & 7).
// ===========================================================================
__global__ __launch_bounds__(256) void round_perm_k(
    const float4* __restrict__ in, float* __restrict__ out, int n4)
{
    const int i = blockIdx.x * 256 + threadIdx.x;
    if (i < n4) {
        float4 v = in[i];
        const size_t f = (size_t)i * 4;
        float vv[4] = {rnd_tf32(v.x), rnd_tf32(v.y), rnd_tf32(v.z), rnd_tf32(v.w)};
#pragma unroll
        for (int j = 0; j < 4; j++) {
            const size_t fj = f + j;
            const int k7 = (int)(fj & 7);
            out[fj - k7 + kperm(k7)] = vv[j];
        }
    }
}

// ===========================================================================
// Weight transpose + tf32 round + K-pair permutation on output column
// (output col = original row r = GEMM K-dim): in [R,C] -> out [C,R].
// ===========================================================================
__global__ __launch_bounds__(256) void transpose_k(
    const float* __restrict__ in, float* __restrict__ out, int R, int C)
{
    __shared__ float tile[32][33];
    const int c0 = blockIdx.x * 32, r0 = blockIdx.y * 32;
    const int x = threadIdx.x, y = threadIdx.y;  // 32 x 8
#pragma unroll
    for (int i = 0; i < 32; i += 8)
        tile[y + i][x] = in[(size_t)(r0 + y + i) * C + c0 + x];
    __syncthreads();
    const int xp = (x & ~7) + kperm(x & 7);
#pragma unroll
    for (int i = 0; i < 32; i += 8)
        out[(size_t)(c0 + y + i) * R + r0 + xp] = rnd_tf32(tile[x][y + i]);
}

// ===========================================================================
// tf32 mma.sync GEMM: C[M,N] = A[M,K] @ Bt[N,K]^T + bias
// K pre-permuted in pair order -> fragment loads are LDS.64.
// Block tile 128(M) x 256(N) x 32(K), 8 warps, warp tile 64x64,
// double-buffered cp.async, mainloop unrolled x2 (static stage addressing).
// ===========================================================================
#define GM 128
#define GN 256
#define GKC 32
#define TST 40                                       // 40 % 32 == 8: LDS.64 conflict-free
#define A_FLOATS (GM * TST)                          // 5120
#define B_FLOATS (GN * TST)                          // 10240
#define STAGE_FLOATS (A_FLOATS + B_FLOATS)           // 15360
#define SMEM_GEMM (2 * STAGE_FLOATS * 4)             // 122880 bytes

template <int RND>
__global__ __launch_bounds__(256) void gemm_mma(
    const float* __restrict__ A, const float* __restrict__ Bt,
    const float* __restrict__ bias, float* __restrict__ C,
    int K, int N)
{
    extern __shared__ float smf[];
    const uint32_t smem_base = smem_u32(smf);
    const int tid  = threadIdx.x;
    const int wid  = tid >> 5;
    const int lane = tid & 31;
    const int wm   = wid >> 2;          // 0..1  (64 M-rows each)
    const int wn   = wid & 3;           // 0..3  (64 N-cols each)
    const int gid  = lane >> 2;
    const int tig  = lane & 3;
    const int m0 = blockIdx.y * GM;
    const int n0 = blockIdx.x * GN;

    const float* Ag = A + (size_t)m0 * K;
    const float* Bg = Bt + (size_t)n0 * K;

    // A: 1024 granules (4/thread), B: 2048 granules (8/thread); g -> row g>>3, c4 g&7
    auto issue_stage = [&](int i, uint32_t sb) {
        const int k0 = i * GKC;
#pragma unroll
        for (int u = 0; u < 4; u++) {
            const int g = tid + u * 256;
            const int row = g >> 3, c4 = g & 7;
            cp16(sb + (uint32_t)(row * TST * 4 + c4 * 16),
                 Ag + (size_t)row * K + k0 + c4 * 4);
        }
        const uint32_t sbB = sb + A_FLOATS * 4;
#pragma unroll
        for (int u = 0; u < 8; u++) {
            const int g = tid + u * 256;
            const int row = g >> 3, c4 = g & 7;
            cp16(sbB + (uint32_t)(row * TST * 4 + c4 * 16),
                 Bg + (size_t)row * K + k0 + c4 * 4);
        }
        CP_COMMIT();
    };

    float acc[4][8][4];
#pragma unroll
    for (int mt = 0; mt < 4; mt++)
#pragma unroll
        for (int nt = 0; nt < 8; nt++)
#pragma unroll
            for (int r = 0; r < 4; r++) acc[mt][nt][r] = 0.f;

    auto compute_stage = [&](const float* stage) {
        const uint32_t* As = (const uint32_t*)stage;
        const uint32_t* Bs = As + A_FLOATS;
#pragma unroll
        for (int ks = 0; ks < 4; ks++) {
            uint32_t af[4][4];
#pragma unroll
            for (int mt = 0; mt < 4; mt++) {
                const uint32_t* pa = As + (wm * 64 + mt * 16 + gid) * TST + ks * 8 + tig * 2;
                const uint2 lo = *(const uint2*)pa;
                const uint2 hi = *(const uint2*)(pa + 8 * TST);
                af[mt][0] = lo.x; af[mt][1] = hi.x;
                af[mt][2] = lo.y; af[mt][3] = hi.y;
            }
            uint32_t bf[8][2];
#pragma unroll
            for (int nt = 0; nt < 8; nt++) {
                const uint32_t* pb = Bs + (wn * 64 + nt * 8 + gid) * TST + ks * 8 + tig * 2;
                const uint2 b = *(const uint2*)pb;
                bf[nt][0] = b.x; bf[nt][1] = b.y;
            }
#pragma unroll
            for (int mt = 0; mt < 4; mt++)
#pragma unroll
                for (int nt = 0; nt < 8; nt++)
                    mma_tf32(acc[mt][nt], af[mt], bf[nt]);
        }
    };

    const int niter = K / GKC;                 // 32 or 128: always even
    const uint32_t sb0 = smem_base;
    const uint32_t sb1 = smem_base + STAGE_FLOATS * 4;
    const float* st0 = smf;
    const float* st1 = smf + STAGE_FLOATS;

    issue_stage(0, sb0);
    for (int i = 0; i < niter; i += 2) {
        // even stage -> buffer 0
        CP_WAIT0();
        __syncthreads();
        if (i + 1 < niter) issue_stage(i + 1, sb1);
        compute_stage(st0);
        // odd stage -> buffer 1
        CP_WAIT0();
        __syncthreads();
        if (i + 2 < niter) issue_stage(i + 2, sb0);
        compute_stage(st1);
    }

#pragma unroll
    for (int mt = 0; mt < 4; mt++) {
        const int r = m0 + wm * 64 + mt * 16 + gid;
#pragma unroll
        for (int nt = 0; nt < 8; nt++) {
            const int c = n0 + wn * 64 + nt * 8 + tig * 2;
            const float bx = bias[c], by = bias[c + 1];
            float2 o0, o1;
            o0.x = acc[mt][nt][0] + bx; o0.y = acc[mt][nt][1] + by;
            o1.x = acc[mt][nt][2] + bx; o1.y = acc[mt][nt][3] + by;
            if (RND) {
                o0.x = rnd_tf32(o0.x); o0.y = rnd_tf32(o0.y);
                o1.x = rnd_tf32(o1.x); o1.y = rnd_tf32(o1.y);
            }
            *(float2*)(C + (size_t)r * N + c) = o0;
            *(float2*)(C + (size_t)(r + 8) * N + c) = o1;
        }
    }
}

// ===========================================================================
// Tensor-core flash attention (tf32 mma.sync).  Q/K/V in NATURAL layout.
// Output written with K-pair-permuted columns (feeds the out-proj GEMM).
// Grid (L/64, H, B), 128 threads (4 warps).
// ===========================================================================
#define QK_ST 68
#define V_ST  72
#define ATTN_SMEM ((2 * 64 * QK_ST + 64 * V_ST) * 4)   // 53248 bytes

__global__ __launch_bounds__(128) void attn_tc(
    const float* __restrict__ Q, const float* __restrict__ K,
    const float* __restrict__ V, float* __restrict__ O)
{
    extern __shared__ float sm[];
    float* Qs = sm;                        // [64][QK_ST]
    float* Ks = Qs + 64 * QK_ST;           // [64][QK_ST]
    float* Vs = Ks + 64 * QK_ST;           // [64][V_ST]
    float* Ps = Qs;                        // alias (Q is register-resident in loop)

    const int tid  = threadIdx.x;
    const int wid  = tid >> 5;
    const int lane = tid & 31;
    const int gid  = lane >> 2;
    const int tig  = lane & 3;
    const int q0 = blockIdx.x * 64;
    const int h  = blockIdx.y;
    const int b  = blockIdx.z;

    const float* Qg = Q + ((size_t)b * Lq + q0) * DHK + h * DK;
    const float* Kg = K + ((size_t)b * Sk) * DHK + h * DK;
    const float* Vg = V + ((size_t)b * Sk) * DHK + h * DK;

    for (int g = tid; g < 64 * 16; g += 128) {
        const int r = g >> 4, e4 = g & 15;
        float4 v = *(const float4*)(Qg + (size_t)r * DHK + e4 * 4);
        *(float4*)&Qs[r * QK_ST + e4 * 4] = v;
    }
    __syncthreads();

    const int r0 = wid * 16 + gid;
    uint32_t qf[8][4];
#pragma unroll
    for (int k0 = 0; k0 < 8; k0++) {
        qf[k0][0] = __float_as_uint(Qs[r0 * QK_ST + k0 * 8 + tig] * 0.125f);
        qf[k0][1] = __float_as_uint(Qs[(r0 + 8) * QK_ST + k0 * 8 + tig] * 0.125f);
        qf[k0][2] = __float_as_uint(Qs[r0 * QK_ST + k0 * 8 + tig + 4] * 0.125f);
        qf[k0][3] = __float_as_uint(Qs[(r0 + 8) * QK_ST + k0 * 8 + tig + 4] * 0.125f);
    }

    float m0 = -INFINITY, m1 = -INFINITY, l0 = 0.f, l1 = 0.f;
    float acc[8][4];
#pragma unroll
    for (int nt = 0; nt < 8; nt++)
#pragma unroll
        for (int r = 0; r < 4; r++) acc[nt][r] = 0.f;

    for (int s0 = 0; s0 < Sk; s0 += 64) {
        __syncthreads();
        for (int g = tid; g < 64 * 16; g += 128) {
            const int r = g >> 4, e4 = g & 15;
            float4 kv = *(const float4*)(Kg + (size_t)(s0 + r) * DHK + e4 * 4);
            *(float4*)&Ks[r * QK_ST + e4 * 4] = kv;
            float4 vv = *(const float4*)(Vg + (size_t)(s0 + r) * DHK + e4 * 4);
            *(float4*)&Vs[r * V_ST + e4 * 4] = vv;
        }
        __syncthreads();

        float sc[8][4];
#pragma unroll
        for (int nt = 0; nt < 8; nt++)
#pragma unroll
            for (int r = 0; r < 4; r++) sc[nt][r] = 0.f;
#pragma unroll
        for (int k0 = 0; k0 < 8; k0++) {
#pragma unroll
            for (int nt = 0; nt < 8; nt++) {
                const uint32_t* pk =
                    (const uint32_t*)Ks + (nt * 8 + gid) * QK_ST + k0 * 8 + tig;
                uint32_t bf[2] = {pk[0], pk[4]};
                mma_tf32(sc[nt], qf[k0], bf);
            }
        }

        float mx0 = -INFINITY, mx1 = -INFINITY;
#pragma unroll
        for (int nt = 0; nt < 8; nt++) {
            mx0 = fmaxf(mx0, fmaxf(sc[nt][0], sc[nt][1]));
            mx1 = fmaxf(mx1, fmaxf(sc[nt][2], sc[nt][3]));
        }
        mx0 = fmaxf(mx0, __shfl_xor_sync(0xffffffffu, mx0, 1));
        mx0 = fmaxf(mx0, __shfl_xor_sync(0xffffffffu, mx0, 2));
        mx1 = fmaxf(mx1, __shfl_xor_sync(0xffffffffu, mx1, 1));
        mx1 = fmaxf(mx1, __shfl_xor_sync(0xffffffffu, mx1, 2));
        const float mn0 = fmaxf(m0, mx0), mn1 = fmaxf(m1, mx1);
        const float f0 = __expf(m0 - mn0), f1 = __expf(m1 - mn1);
        float sum0 = 0.f, sum1 = 0.f;
#pragma unroll
        for (int nt = 0; nt < 8; nt++) {
            sc[nt][0] = __expf(sc[nt][0] - mn0);
            sc[nt][1] = __expf(sc[nt][1] - mn0);
            sc[nt][2] = __expf(sc[nt][2] - mn1);
            sc[nt][3] = __expf(sc[nt][3] - mn1);
            sum0 += sc[nt][0] + sc[nt][1];
            sum1 += sc[nt][2] + sc[nt][3];
        }
        sum0 += __shfl_xor_sync(0xffffffffu, sum0, 1);
        sum0 += __shfl_xor_sync(0xffffffffu, sum0, 2);
        sum1 += __shfl_xor_sync(0xffffffffu, sum1, 1);
        sum1 += __shfl_xor_sync(0xffffffffu, sum1, 2);
        l0 = l0 * f0 + sum0;  m0 = mn0;
        l1 = l1 * f1 + sum1;  m1 = mn1;

#pragma unroll
        for (int nt = 0; nt < 8; nt++) {
            acc[nt][0] *= f0; acc[nt][1] *= f0;
            acc[nt][2] *= f1; acc[nt][3] *= f1;
        }

#pragma unroll
        for (int nt = 0; nt < 8; nt++) {
            float2 p0, p1;
            p0.x = rnd_tf32(sc[nt][0]); p0.y = rnd_tf32(sc[nt][1]);
            p1.x = rnd_tf32(sc[nt][2]); p1.y = rnd_tf32(sc[nt][3]);
            *(float2*)&Ps[r0 * QK_ST + nt * 8 + tig * 2] = p0;
            *(float2*)&Ps[(r0 + 8) * QK_ST + nt * 8 + tig * 2] = p1;
        }
        __syncwarp();

#pragma unroll
        for (int k0 = 0; k0 < 8; k0++) {
            const uint32_t* pp = (const uint32_t*)Ps + r0 * QK_ST + k0 * 8 + tig;
            uint32_t af[4];
            af[0] = pp[0];
            af[1] = pp[8 * QK_ST];
            af[2] = pp[4];
            af[3] = pp[8 * QK_ST + 4];
#pragma unroll
            for (int nt = 0; nt < 8; nt++) {
                const uint32_t* pv =
                    (const uint32_t*)Vs + (k0 * 8 + tig) * V_ST + nt * 8 + gid;
                uint32_t bf[2] = {pv[0], pv[4 * V_ST]};
                mma_tf32(acc[nt], af, bf);
            }
        }
    }

    // Epilogue: normalize, round, store with K-pair-permuted columns
    // (this tensor is the A operand / K-dim of the out-proj GEMM).
    const float inv0 = 1.f / l0, inv1 = 1.f / l1;
    float* Og = O + ((size_t)b * Lq + q0 + r0) * DHK + h * DK;
    const int cpa = kperm(2 * tig);
    const int cpb = kperm(2 * tig + 1);
#pragma unroll
    for (int nt = 0; nt < 8; nt++) {
        Og[nt * 8 + cpa] = rnd_tf32(acc[nt][0] * inv0);
        Og[nt * 8 + cpb] = rnd_tf32(acc[nt][1] * inv0);
        Og[(size_t)8 * DHK + nt * 8 + cpa] = rnd_tf32(acc[nt][2] * inv1);
        Og[(size_t)8 * DHK + nt * 8 + cpb] = rnd_tf32(acc[nt][3] * inv1);
    }
}

// ===========================================================================
// Launch
// ===========================================================================
extern "C" void kernel_launch(void* const* d_in, const int* in_sizes, int n_in,
                              void* d_out, int out_size)
{
    const float* target = (const float*)d_in[0];
    const float* source = (const float*)d_in[1];
    const float* Wq = (const float*)d_in[2];
    const float* bq = (const float*)d_in[3];
    const float* Wk = (const float*)d_in[4];
    const float* bk = (const float*)d_in[5];
    const float* Wv = (const float*)d_in[6];
    const float* bv = (const float*)d_in[7];
    const float* Wo = (const float*)d_in[8];
    const float* bo = (const float*)d_in[9];
    float* out = (float*)d_out;

    float* Qb; cudaGetSymbolAddress((void**)&Qb, g_Q);
    float* Kb; cudaGetSymbolAddress((void**)&Kb, g_K);
    float* Vb; cudaGetSymbolAddress((void**)&Vb, g_V);
    float* Cb; cudaGetSymbolAddress((void**)&Cb, g_C);
    float* WT; cudaGetSymbolAddress((void**)&WT, g_WT);
    float* Sr; cudaGetSymbolAddress((void**)&Sr, g_Sr);

    const int ML = Bz * Lq;   // 16384
    const int MS = Bz * Sk;   // 8192

    cudaFuncSetAttribute(gemm_mma<0>, cudaFuncAttributeMaxDynamicSharedMemorySize, SMEM_GEMM);
    cudaFuncSetAttribute(gemm_mma<1>, cudaFuncAttributeMaxDynamicSharedMemorySize, SMEM_GEMM);
    cudaFuncSetAttribute(attn_tc, cudaFuncAttributeMaxDynamicSharedMemorySize, ATTN_SMEM);

    // Round + K-permute inputs once
    {
        const int nt4 = ML * DM / 4;        // 4M
        round_perm_k<<<nt4 / 256, 256>>>((const float4*)target, Cb, nt4);
        const int ns4 = MS * DLLM / 4;      // 8M
        round_perm_k<<<ns4 / 256, 256>>>((const float4*)source, Sr, ns4);
    }

    // Q = round(target) @ Wq + bq  (rounded natural-N output)
    transpose_k<<<dim3(DHK / 32, DM / 32), dim3(32, 8)>>>(Wq, WT, DM, DHK);
    gemm_mma<1><<<dim3(DHK / GN, ML / GM), 256, SMEM_GEMM>>>(Cb, WT, bq, Qb, DM, DHK);

    // K = round(source) @ Wk + bk
    transpose_k<<<dim3(DHK / 32, DLLM / 32), dim3(32, 8)>>>(Wk, WT, DLLM, DHK);
    gemm_mma<1><<<dim3(DHK / GN, MS / GM), 256, SMEM_GEMM>>>(Sr, WT, bk, Kb, DLLM, DHK);

    // V = round(source) @ Wv + bv
    transpose_k<<<dim3(DHK / 32, DLLM / 32), dim3(32, 8)>>>(Wv, WT, DLLM, DHK);
    gemm_mma<1><<<dim3(DHK / GN, MS / GM), 256, SMEM_GEMM>>>(Sr, WT, bv, Vb, DLLM, DHK);

    // Attention (overwrites Cb; output rounded + K-permuted for out-proj)
    attn_tc<<<dim3(Lq / 64, NH, Bz), 128, ATTN_SMEM>>>(Qb, Kb, Vb, Cb);

    // out = C @ Wo + bo  (final output: natural, NOT rounded)
    transpose_k<<<dim3(DLLM / 32, DHK / 32), dim3(32, 8)>>>(Wo, WT, DHK, DLLM);
    gemm_mma<0><<<dim3(DLLM / GN, ML / GM), 256, SMEM_GEMM>>>(Cb, WT, bo, out, DHK, DLLM);
}

// round 11
// speedup vs baseline: 1.0466x; 1.0466x over previous
#include <cuda_runtime.h>
#include <cstdint>
#include <math.h>

#define Bz 8
#define Lq 2048
#define Sk 1024
#define DM 1024
#define DLLM 4096
#define NH 16
#define DK 64
#define DHK 1024

// Scratch (allocation-free rule: __device__ globals)
__device__ float g_Q[(size_t)Bz * Lq * DHK];    // 64 MB
__device__ float g_K[(size_t)Bz * Sk * DHK];    // 32 MB
__device__ float g_V[(size_t)Bz * Sk * DHK];    // 32 MB
__device__ float g_C[(size_t)Bz * Lq * DHK];    // 64 MB (perm-rounded target, then attn out)
__device__ float g_WT[(size_t)DLLM * DHK];      // 16 MB (transposed+rounded+K-permuted weight)
__device__ float g_Sr[(size_t)Bz * Sk * DLLM];  // 128 MB (perm-rounded source)

// ===========================================================================
// Helpers
// ===========================================================================
__device__ __forceinline__ uint32_t smem_u32(const void* p) {
    uint32_t a;
    asm("{ .reg .u64 t; cvta.to.shared.u64 t, %1; cvt.u32.u64 %0, t; }" : "=r"(a) : "l"(p));
    return a;
}
__device__ __forceinline__ void cp16(uint32_t dst, const void* src) {
    asm volatile("cp.async.cg.shared.global [%0], [%1], 16;" :: "r"(dst), "l"(src));
}
#define CP_COMMIT() asm volatile("cp.async.commit_group;" ::: "memory")
#define CP_WAIT0()  asm volatile("cp.async.wait_group 0;" ::: "memory")

__device__ __forceinline__ float rnd_tf32(float x) {
    uint32_t r;
    asm("cvt.rna.tf32.f32 %0, %1;" : "=r"(r) : "f"(x));
    return __uint_as_float(r);
}
// K-permutation within groups of 8: pos of original index j is p(j).
// Layout order becomes [0,4,1,5,2,6,3,7] so (k, k+4) pairs are adjacent.
__device__ __forceinline__ int kperm(int j) { return (j < 4) ? 2 * j : 2 * j - 7; }

__device__ __forceinline__ void mma_tf32(float c[4], const uint32_t a[4], const uint32_t b[2]) {
    asm volatile(
        "mma.sync.aligned.m16n8k8.row.col.f32.tf32.tf32.f32 "
        "{%0,%1,%2,%3}, {%4,%5,%6,%7}, {%8,%9}, {%0,%1,%2,%3};"
        : "+f"(c[0]), "+f"(c[1]), "+f"(c[2]), "+f"(c[3])
        : "r"(a[0]), "r"(a[1]), "r"(a[2]), "r"(a[3]), "r"(b[0]), "r"(b[1]));
}

// ===========================================================================
// Elementwise tf32 round + K-pair permutation (row stride divisible by 8,
// so flat_index & 7 == k & 7).
// ===========================================================================
__global__ __launch_bounds__(256) void round_perm_k(
    const float4* __restrict__ in, float* __restrict__ out, int n4)
{
    const int i = blockIdx.x * 256 + threadIdx.x;
    if (i < n4) {
        float4 v = in[i];
        const size_t f = (size_t)i * 4;
        float vv[4] = {rnd_tf32(v.x), rnd_tf32(v.y), rnd_tf32(v.z), rnd_tf32(v.w)};
#pragma unroll
        for (int j = 0; j < 4; j++) {
            const size_t fj = f + j;
            const int k7 = (int)(fj & 7);
            out[fj - k7 + kperm(k7)] = vv[j];
        }
    }
}

// ===========================================================================
// Weight transpose + tf32 round + K-pair permutation on output column
// (output col = original row r = GEMM K-dim): in [R,C] -> out [C,R].
// ===========================================================================
__global__ __launch_bounds__(256) void transpose_k(
    const float* __restrict__ in, float* __restrict__ out, int R, int C)
{
    __shared__ float tile[32][33];
    const int c0 = blockIdx.x * 32, r0 = blockIdx.y * 32;
    const int x = threadIdx.x, y = threadIdx.y;  // 32 x 8
#pragma unroll
    for (int i = 0; i < 32; i += 8)
        tile[y + i][x] = in[(size_t)(r0 + y + i) * C + c0 + x];
    __syncthreads();
    const int xp = (x & ~7) + kperm(x & 7);
#pragma unroll
    for (int i = 0; i < 32; i += 8)
        out[(size_t)(c0 + y + i) * R + r0 + xp] = rnd_tf32(tile[x][y + i]);
}

// ===========================================================================
// tf32 mma.sync GEMM: C[M,N] = A[M,K] @ Bt[N,K]^T + bias
// K pre-permuted in pair order -> fragment loads are LDS.64.
// Block tile 128x128x32, 4 warps (2M x 2N), warp tile 64x64 (0.5 LDS/HMMA),
// double-buffered cp.async, mainloop unrolled x2 (static stage addressing).
// 2 CTAs/SM (80 KB smem, ~236 regs @ 128 threads).
// ===========================================================================
#define GM 128
#define GN 128
#define GKC 32
#define TST 40                                       // 40 % 32 == 8: LDS.64 conflict-free
#define A_FLOATS (GM * TST)                          // 5120
#define B_FLOATS (GN * TST)                          // 5120
#define STAGE_FLOATS (A_FLOATS + B_FLOATS)           // 10240
#define SMEM_GEMM (2 * STAGE_FLOATS * 4)             // 81920 bytes

template <int RND>
__global__ __launch_bounds__(128, 2) void gemm_mma(
    const float* __restrict__ A, const float* __restrict__ Bt,
    const float* __restrict__ bias, float* __restrict__ C,
    int K, int N)
{
    extern __shared__ float smf[];
    const uint32_t smem_base = smem_u32(smf);
    const int tid  = threadIdx.x;
    const int wid  = tid >> 5;
    const int lane = tid & 31;
    const int wm   = wid >> 1;          // 0..1  (64 M-rows each)
    const int wn   = wid & 1;           // 0..1  (64 N-cols each)
    const int gid  = lane >> 2;
    const int tig  = lane & 3;
    const int m0 = blockIdx.y * GM;
    const int n0 = blockIdx.x * GN;

    const float* Ag = A + (size_t)m0 * K;
    const float* Bg = Bt + (size_t)n0 * K;

    // A: 1024 granules (8/thread), B: 1024 granules (8/thread); g -> row g>>3, c4 g&7
    auto issue_stage = [&](int i, uint32_t sb) {
        const int k0 = i * GKC;
#pragma unroll
        for (int u = 0; u < 8; u++) {
            const int g = tid + u * 128;
            const int row = g >> 3, c4 = g & 7;
            cp16(sb + (uint32_t)(row * TST * 4 + c4 * 16),
                 Ag + (size_t)row * K + k0 + c4 * 4);
        }
        const uint32_t sbB = sb + A_FLOATS * 4;
#pragma unroll
        for (int u = 0; u < 8; u++) {
            const int g = tid + u * 128;
            const int row = g >> 3, c4 = g & 7;
            cp16(sbB + (uint32_t)(row * TST * 4 + c4 * 16),
                 Bg + (size_t)row * K + k0 + c4 * 4);
        }
        CP_COMMIT();
    };

    float acc[4][8][4];
#pragma unroll
    for (int mt = 0; mt < 4; mt++)
#pragma unroll
        for (int nt = 0; nt < 8; nt++)
#pragma unroll
            for (int r = 0; r < 4; r++) acc[mt][nt][r] = 0.f;

    auto compute_stage = [&](const float* stage) {
        const uint32_t* As = (const uint32_t*)stage;
        const uint32_t* Bs = As + A_FLOATS;
#pragma unroll
        for (int ks = 0; ks < 4; ks++) {
            uint32_t af[4][4];
#pragma unroll
            for (int mt = 0; mt < 4; mt++) {
                const uint32_t* pa = As + (wm * 64 + mt * 16 + gid) * TST + ks * 8 + tig * 2;
                const uint2 lo = *(const uint2*)pa;
                const uint2 hi = *(const uint2*)(pa + 8 * TST);
                af[mt][0] = lo.x; af[mt][1] = hi.x;
                af[mt][2] = lo.y; af[mt][3] = hi.y;
            }
            uint32_t bf[8][2];
#pragma unroll
            for (int nt = 0; nt < 8; nt++) {
                const uint32_t* pb = Bs + (wn * 64 + nt * 8 + gid) * TST + ks * 8 + tig * 2;
                const uint2 b = *(const uint2*)pb;
                bf[nt][0] = b.x; bf[nt][1] = b.y;
            }
#pragma unroll
            for (int mt = 0; mt < 4; mt++)
#pragma unroll
                for (int nt = 0; nt < 8; nt++)
                    mma_tf32(acc[mt][nt], af[mt], bf[nt]);
        }
    };

    const int niter = K / GKC;                 // 32 or 128: always even
    const uint32_t sb0 = smem_base;
    const uint32_t sb1 = smem_base + STAGE_FLOATS * 4;
    const float* st0 = smf;
    const float* st1 = smf + STAGE_FLOATS;

    issue_stage(0, sb0);
    for (int i = 0; i < niter; i += 2) {
        // even stage -> buffer 0
        CP_WAIT0();
        __syncthreads();
        if (i + 1 < niter) issue_stage(i + 1, sb1);
        compute_stage(st0);
        // odd stage -> buffer 1
        CP_WAIT0();
        __syncthreads();
        if (i + 2 < niter) issue_stage(i + 2, sb0);
        compute_stage(st1);
    }

#pragma unroll
    for (int mt = 0; mt < 4; mt++) {
        const int r = m0 + wm * 64 + mt * 16 + gid;
#pragma unroll
        for (int nt = 0; nt < 8; nt++) {
            const int c = n0 + wn * 64 + nt * 8 + tig * 2;
            const float bx = bias[c], by = bias[c + 1];
            float2 o0, o1;
            o0.x = acc[mt][nt][0] + bx; o0.y = acc[mt][nt][1] + by;
            o1.x = acc[mt][nt][2] + bx; o1.y = acc[mt][nt][3] + by;
            if (RND) {
                o0.x = rnd_tf32(o0.x); o0.y = rnd_tf32(o0.y);
                o1.x = rnd_tf32(o1.x); o1.y = rnd_tf32(o1.y);
            }
            *(float2*)(C + (size_t)r * N + c) = o0;
            *(float2*)(C + (size_t)(r + 8) * N + c) = o1;
        }
    }
}

// ===========================================================================
// Tensor-core flash attention (tf32 mma.sync).  Q/K/V in NATURAL layout.
// Output written with K-pair-permuted columns (feeds the out-proj GEMM).
// Grid (L/64, H, B), 128 threads (4 warps).
// ===========================================================================
#define QK_ST 68
#define V_ST  72
#define ATTN_SMEM ((2 * 64 * QK_ST + 64 * V_ST) * 4)   // 53248 bytes

__global__ __launch_bounds__(128) void attn_tc(
    const float* __restrict__ Q, const float* __restrict__ K,
    const float* __restrict__ V, float* __restrict__ O)
{
    extern __shared__ float sm[];
    float* Qs = sm;                        // [64][QK_ST]
    float* Ks = Qs + 64 * QK_ST;           // [64][QK_ST]
    float* Vs = Ks + 64 * QK_ST;           // [64][V_ST]
    float* Ps = Qs;                        // alias (Q is register-resident in loop)

    const int tid  = threadIdx.x;
    const int wid  = tid >> 5;
    const int lane = tid & 31;
    const int gid  = lane >> 2;
    const int tig  = lane & 3;
    const int q0 = blockIdx.x * 64;
    const int h  = blockIdx.y;
    const int b  = blockIdx.z;

    const float* Qg = Q + ((size_t)b * Lq + q0) * DHK + h * DK;
    const float* Kg = K + ((size_t)b * Sk) * DHK + h * DK;
    const float* Vg = V + ((size_t)b * Sk) * DHK + h * DK;

    for (int g = tid; g < 64 * 16; g += 128) {
        const int r = g >> 4, e4 = g & 15;
        float4 v = *(const float4*)(Qg + (size_t)r * DHK + e4 * 4);
        *(float4*)&Qs[r * QK_ST + e4 * 4] = v;
    }
    __syncthreads();

    const int r0 = wid * 16 + gid;
    uint32_t qf[8][4];
#pragma unroll
    for (int k0 = 0; k0 < 8; k0++) {
        qf[k0][0] = __float_as_uint(Qs[r0 * QK_ST + k0 * 8 + tig] * 0.125f);
        qf[k0][1] = __float_as_uint(Qs[(r0 + 8) * QK_ST + k0 * 8 + tig] * 0.125f);
        qf[k0][2] = __float_as_uint(Qs[r0 * QK_ST + k0 * 8 + tig + 4] * 0.125f);
        qf[k0][3] = __float_as_uint(Qs[(r0 + 8) * QK_ST + k0 * 8 + tig + 4] * 0.125f);
    }

    float m0 = -INFINITY, m1 = -INFINITY, l0 = 0.f, l1 = 0.f;
    float acc[8][4];
#pragma unroll
    for (int nt = 0; nt < 8; nt++)
#pragma unroll
        for (int r = 0; r < 4; r++) acc[nt][r] = 0.f;

    for (int s0 = 0; s0 < Sk; s0 += 64) {
        __syncthreads();
        for (int g = tid; g < 64 * 16; g += 128) {
            const int r = g >> 4, e4 = g & 15;
            float4 kv = *(const float4*)(Kg + (size_t)(s0 + r) * DHK + e4 * 4);
            *(float4*)&Ks[r * QK_ST + e4 * 4] = kv;
            float4 vv = *(const float4*)(Vg + (size_t)(s0 + r) * DHK + e4 * 4);
            *(float4*)&Vs[r * V_ST + e4 * 4] = vv;
        }
        __syncthreads();

        float sc[8][4];
#pragma unroll
        for (int nt = 0; nt < 8; nt++)
#pragma unroll
            for (int r = 0; r < 4; r++) sc[nt][r] = 0.f;
#pragma unroll
        for (int k0 = 0; k0 < 8; k0++) {
#pragma unroll
            for (int nt = 0; nt < 8; nt++) {
                const uint32_t* pk =
                    (const uint32_t*)Ks + (nt * 8 + gid) * QK_ST + k0 * 8 + tig;
                uint32_t bf[2] = {pk[0], pk[4]};
                mma_tf32(sc[nt], qf[k0], bf);
            }
        }

        float mx0 = -INFINITY, mx1 = -INFINITY;
#pragma unroll
        for (int nt = 0; nt < 8; nt++) {
            mx0 = fmaxf(mx0, fmaxf(sc[nt][0], sc[nt][1]));
            mx1 = fmaxf(mx1, fmaxf(sc[nt][2], sc[nt][3]));
        }
        mx0 = fmaxf(mx0, __shfl_xor_sync(0xffffffffu, mx0, 1));
        mx0 = fmaxf(mx0, __shfl_xor_sync(0xffffffffu, mx0, 2));
        mx1 = fmaxf(mx1, __shfl_xor_sync(0xffffffffu, mx1, 1));
        mx1 = fmaxf(mx1, __shfl_xor_sync(0xffffffffu, mx1, 2));
        const float mn0 = fmaxf(m0, mx0), mn1 = fmaxf(m1, mx1);
        const float f0 = __expf(m0 - mn0), f1 = __expf(m1 - mn1);
        float sum0 = 0.f, sum1 = 0.f;
#pragma unroll
        for (int nt = 0; nt < 8; nt++) {
            sc[nt][0] = __expf(sc[nt][0] - mn0);
            sc[nt][1] = __expf(sc[nt][1] - mn0);
            sc[nt][2] = __expf(sc[nt][2] - mn1);
            sc[nt][3] = __expf(sc[nt][3] - mn1);
            sum0 += sc[nt][0] + sc[nt][1];
            sum1 += sc[nt][2] + sc[nt][3];
        }
        sum0 += __shfl_xor_sync(0xffffffffu, sum0, 1);
        sum0 += __shfl_xor_sync(0xffffffffu, sum0, 2);
        sum1 += __shfl_xor_sync(0xffffffffu, sum1, 1);
        sum1 += __shfl_xor_sync(0xffffffffu, sum1, 2);
        l0 = l0 * f0 + sum0;  m0 = mn0;
        l1 = l1 * f1 + sum1;  m1 = mn1;

#pragma unroll
        for (int nt = 0; nt < 8; nt++) {
            acc[nt][0] *= f0; acc[nt][1] *= f0;
            acc[nt][2] *= f1; acc[nt][3] *= f1;
        }

#pragma unroll
        for (int nt = 0; nt < 8; nt++) {
            float2 p0, p1;
            p0.x = rnd_tf32(sc[nt][0]); p0.y = rnd_tf32(sc[nt][1]);
            p1.x = rnd_tf32(sc[nt][2]); p1.y = rnd_tf32(sc[nt][3]);
            *(float2*)&Ps[r0 * QK_ST + nt * 8 + tig * 2] = p0;
            *(float2*)&Ps[(r0 + 8) * QK_ST + nt * 8 + tig * 2] = p1;
        }
        __syncwarp();

#pragma unroll
        for (int k0 = 0; k0 < 8; k0++) {
            const uint32_t* pp = (const uint32_t*)Ps + r0 * QK_ST + k0 * 8 + tig;
            uint32_t af[4];
            af[0] = pp[0];
            af[1] = pp[8 * QK_ST];
            af[2] = pp[4];
            af[3] = pp[8 * QK_ST + 4];
#pragma unroll
            for (int nt = 0; nt < 8; nt++) {
                const uint32_t* pv =
                    (const uint32_t*)Vs + (k0 * 8 + tig) * V_ST + nt * 8 + gid;
                uint32_t bf[2] = {pv[0], pv[4 * V_ST]};
                mma_tf32(acc[nt], af, bf);
            }
        }
    }

    // Epilogue: normalize, round, store with K-pair-permuted columns
    // (this tensor is the A operand / K-dim of the out-proj GEMM).
    const float inv0 = 1.f / l0, inv1 = 1.f / l1;
    float* Og = O + ((size_t)b * Lq + q0 + r0) * DHK + h * DK;
    const int cpa = kperm(2 * tig);
    const int cpb = kperm(2 * tig + 1);
#pragma unroll
    for (int nt = 0; nt < 8; nt++) {
        Og[nt * 8 + cpa] = rnd_tf32(acc[nt][0] * inv0);
        Og[nt * 8 + cpb] = rnd_tf32(acc[nt][1] * inv0);
        Og[(size_t)8 * DHK + nt * 8 + cpa] = rnd_tf32(acc[nt][2] * inv1);
        Og[(size_t)8 * DHK + nt * 8 + cpb] = rnd_tf32(acc[nt][3] * inv1);
    }
}

// ===========================================================================
// Launch
// ===========================================================================
extern "C" void kernel_launch(void* const* d_in, const int* in_sizes, int n_in,
                              void* d_out, int out_size)
{
    const float* target = (const float*)d_in[0];
    const float* source = (const float*)d_in[1];
    const float* Wq = (const float*)d_in[2];
    const float* bq = (const float*)d_in[3];
    const float* Wk = (const float*)d_in[4];
    const float* bk = (const float*)d_in[5];
    const float* Wv = (const float*)d_in[6];
    const float* bv = (const float*)d_in[7];
    const float* Wo = (const float*)d_in[8];
    const float* bo = (const float*)d_in[9];
    float* out = (float*)d_out;

    float* Qb; cudaGetSymbolAddress((void**)&Qb, g_Q);
    float* Kb; cudaGetSymbolAddress((void**)&Kb, g_K);
    float* Vb; cudaGetSymbolAddress((void**)&Vb, g_V);
    float* Cb; cudaGetSymbolAddress((void**)&Cb, g_C);
    float* WT; cudaGetSymbolAddress((void**)&WT, g_WT);
    float* Sr; cudaGetSymbolAddress((void**)&Sr, g_Sr);

    const int ML = Bz * Lq;   // 16384
    const int MS = Bz * Sk;   // 8192

    cudaFuncSetAttribute(gemm_mma<0>, cudaFuncAttributeMaxDynamicSharedMemorySize, SMEM_GEMM);
    cudaFuncSetAttribute(gemm_mma<1>, cudaFuncAttributeMaxDynamicSharedMemorySize, SMEM_GEMM);
    cudaFuncSetAttribute(attn_tc, cudaFuncAttributeMaxDynamicSharedMemorySize, ATTN_SMEM);

    // Round + K-permute inputs once
    {
        const int nt4 = ML * DM / 4;        // 4M
        round_perm_k<<<nt4 / 256, 256>>>((const float4*)target, Cb, nt4);
        const int ns4 = MS * DLLM / 4;      // 8M
        round_perm_k<<<ns4 / 256, 256>>>((const float4*)source, Sr, ns4);
    }

    // Q = round(target) @ Wq + bq  (rounded natural-N output)
    transpose_k<<<dim3(DHK / 32, DM / 32), dim3(32, 8)>>>(Wq, WT, DM, DHK);
    gemm_mma<1><<<dim3(DHK / GN, ML / GM), 128, SMEM_GEMM>>>(Cb, WT, bq, Qb, DM, DHK);

    // K = round(source) @ Wk + bk
    transpose_k<<<dim3(DHK / 32, DLLM / 32), dim3(32, 8)>>>(Wk, WT, DLLM, DHK);
    gemm_mma<1><<<dim3(DHK / GN, MS / GM), 128, SMEM_GEMM>>>(Sr, WT, bk, Kb, DLLM, DHK);

    // V = round(source) @ Wv + bv
    transpose_k<<<dim3(DHK / 32, DLLM / 32), dim3(32, 8)>>>(Wv, WT, DLLM, DHK);
    gemm_mma<1><<<dim3(DHK / GN, MS / GM), 128, SMEM_GEMM>>>(Sr, WT, bv, Vb, DLLM, DHK);

    // Attention (overwrites Cb; output rounded + K-permuted for out-proj)
    attn_tc<<<dim3(Lq / 64, NH, Bz), 128, ATTN_SMEM>>>(Qb, Kb, Vb, Cb);

    // out = C @ Wo + bo  (final output: natural, NOT rounded)
    transpose_k<<<dim3(DLLM / 32, DHK / 32), dim3(32, 8)>>>(Wo, WT, DHK, DLLM);
    gemm_mma<0><<<dim3(DLLM / GN, ML / GM), 128, SMEM_GEMM>>>(Cb, WT, bo, out, DHK, DLLM);
}

// round 12
// speedup vs baseline: 1.6206x; 1.5485x over previous
#include <cuda_runtime.h>
#include <cuda_fp16.h>
#include <cstdint>
#include <math.h>

#define Bz 8
#define Lq 2048
#define Sk 1024
#define DM 1024
#define DLLM 4096
#define NH 16
#define DK 64
#define DHK 1024

// Scratch (allocation-free rule: __device__ globals)
__device__ float  g_Q[(size_t)Bz * Lq * DHK];     // 64 MB fp32 (attention input)
__device__ float  g_K[(size_t)Bz * Sk * DHK];     // 32 MB
__device__ float  g_V[(size_t)Bz * Sk * DHK];     // 32 MB
__device__ __half g_H[(size_t)Bz * Lq * DHK];     // 32 MB fp16: target, then attn out
__device__ __half g_WT[(size_t)DLLM * DHK];       // 8 MB fp16 transposed weight
__device__ __half g_Sr[(size_t)Bz * Sk * DLLM];   // 64 MB fp16 source

// ===========================================================================
// Helpers
// ===========================================================================
__device__ __forceinline__ void cp16(uint32_t dst, const void* src) {
    asm volatile("cp.async.cg.shared.global [%0], [%1], 16;" :: "r"(dst), "l"(src));
}
#define CP_COMMIT() asm volatile("cp.async.commit_group;" ::: "memory")
#define CP_WAIT0()  asm volatile("cp.async.wait_group 0;" ::: "memory")

__device__ __forceinline__ uint32_t smem_u32(const void* p) {
    uint32_t a;
    asm("{ .reg .u64 t; cvta.to.shared.u64 t, %1; cvt.u32.u64 %0, t; }" : "=r"(a) : "l"(p));
    return a;
}
__device__ __forceinline__ float rnd_tf32(float x) {
    uint32_t r;
    asm("cvt.rna.tf32.f32 %0, %1;" : "=r"(r) : "f"(x));
    return __uint_as_float(r);
}
// fp16 K-permutation within groups of 16: position of original index k.
// Order [0,1,8,9, 2,3,10,11, 4,5,12,13, 6,7,14,15]: thread t's LDS.64 at
// halves 4t..4t+3 holds original k = 2t, 2t+1, 2t+8, 2t+9.
__device__ __forceinline__ int perm16(int k) {
    return (k < 8) ? ((k >> 1) * 4 + (k & 1)) : (((k - 8) >> 1) * 4 + 2 + (k & 1));
}

__device__ __forceinline__ void mma_f16(float c[4], const uint32_t a[4], const uint32_t b[2]) {
    asm volatile(
        "mma.sync.aligned.m16n8k16.row.col.f32.f16.f16.f32 "
        "{%0,%1,%2,%3}, {%4,%5,%6,%7}, {%8,%9}, {%0,%1,%2,%3};"
        : "+f"(c[0]), "+f"(c[1]), "+f"(c[2]), "+f"(c[3])
        : "r"(a[0]), "r"(a[1]), "r"(a[2]), "r"(a[3]), "r"(b[0]), "r"(b[1]));
}
__device__ __forceinline__ void mma_tf32(float c[4], const uint32_t a[4], const uint32_t b[2]) {
    asm volatile(
        "mma.sync.aligned.m16n8k8.row.col.f32.tf32.tf32.f32 "
        "{%0,%1,%2,%3}, {%4,%5,%6,%7}, {%8,%9}, {%0,%1,%2,%3};"
        : "+f"(c[0]), "+f"(c[1]), "+f"(c[2]), "+f"(c[3])
        : "r"(a[0]), "r"(a[1]), "r"(a[2]), "r"(a[3]), "r"(b[0]), "r"(b[1]));
}

// ===========================================================================
// fp32 -> fp16 with perm16 on (flat & 15).  Row strides divisible by 16.
// Even-k pairs map to adjacent permuted positions -> half2 stores.
// ===========================================================================
__global__ __launch_bounds__(256) void round_perm_k(
    const float4* __restrict__ in, __half* __restrict__ out, int n4)
{
    const int i = blockIdx.x * 256 + threadIdx.x;
    if (i < n4) {
        float4 v = in[i];
        const size_t f = (size_t)i * 4;
        const int k = (int)(f & 15);            // even, k and k+2 in same 16-group
        __half* base = out + (f - k);
        *(__half2*)(base + perm16(k))     = __floats2half2_rn(v.x, v.y);
        *(__half2*)(base + perm16(k + 2)) = __floats2half2_rn(v.z, v.w);
    }
}

// ===========================================================================
// Weight transpose -> fp16 with perm16 on output column (= GEMM K-dim):
// in [R,C] row-major -> out [C,R] fp16.
// ===========================================================================
__global__ __launch_bounds__(256) void transpose_k(
    const float* __restrict__ in, __half* __restrict__ out, int R, int C)
{
    __shared__ float tile[32][33];
    const int c0 = blockIdx.x * 32, r0 = blockIdx.y * 32;
    const int x = threadIdx.x, y = threadIdx.y;  // 32 x 8
#pragma unroll
    for (int i = 0; i < 32; i += 8)
        tile[y + i][x] = in[(size_t)(r0 + y + i) * C + c0 + x];
    __syncthreads();
    const int xp = (x & ~15) + perm16(x & 15);
#pragma unroll
    for (int i = 0; i < 32; i += 8)
        out[(size_t)(c0 + y + i) * R + r0 + xp] = __float2half_rn(tile[x][y + i]);
}

// ===========================================================================
// fp16 mma.sync GEMM: C[M,N] = A[M,K] @ Bt[N,K]^T + bias  (fp32 accum)
// K pre-permuted (perm16) -> all fragment loads are LDS.64.
// Block tile 128x128x64, 4 warps (2Mx2N), warp tile 64x64, m16n8k16,
// double-buffered cp.async, mainloop unrolled x2. 2 CTAs/SM (80KB smem).
// ===========================================================================
#define GM 128
#define GN 128
#define GKC 64
#define TST 80                                       // halves; 160B row: LDS.64 conflict-free
#define A_HALves (GM * TST)                          // 10240 halves = 20480 B
#define STAGE_HALVES (2 * GM * TST)                  // A + B
#define SMEM_GEMM (2 * STAGE_HALVES * 2)             // 81920 bytes

template <int RND>
__global__ __launch_bounds__(128, 2) void gemm_mma(
    const __half* __restrict__ A, const __half* __restrict__ Bt,
    const float* __restrict__ bias, float* __restrict__ C,
    int K, int N)
{
    extern __shared__ __half smh[];
    const uint32_t smem_base = smem_u32(smh);
    const int tid  = threadIdx.x;
    const int wid  = tid >> 5;
    const int lane = tid & 31;
    const int wm   = wid >> 1;          // 0..1  (64 M-rows)
    const int wn   = wid & 1;           // 0..1  (64 N-cols)
    const int gid  = lane >> 2;
    const int tig  = lane & 3;
    const int m0 = blockIdx.y * GM;
    const int n0 = blockIdx.x * GN;

    const __half* Ag = A + (size_t)m0 * K;
    const __half* Bg = Bt + (size_t)n0 * K;

    // Tile row = 64 halves = 128 B = 8 granules of 16B. 1024 granules/operand,
    // 8 per thread. g -> row g>>3, c8 = g&7.
    auto issue_stage = [&](int i, uint32_t sb) {
        const int k0 = i * GKC;
#pragma unroll
        for (int u = 0; u < 8; u++) {
            const int g = tid + u * 128;
            const int row = g >> 3, c8 = g & 7;
            cp16(sb + (uint32_t)(row * TST * 2 + c8 * 16),
                 Ag + (size_t)row * K + k0 + c8 * 8);
        }
        const uint32_t sbB = sb + A_HALves * 2;
#pragma unroll
        for (int u = 0; u < 8; u++) {
            const int g = tid + u * 128;
            const int row = g >> 3, c8 = g & 7;
            cp16(sbB + (uint32_t)(row * TST * 2 + c8 * 16),
                 Bg + (size_t)row * K + k0 + c8 * 8);
        }
        CP_COMMIT();
    };

    float acc[4][8][4];
#pragma unroll
    for (int mt = 0; mt < 4; mt++)
#pragma unroll
        for (int nt = 0; nt < 8; nt++)
#pragma unroll
            for (int r = 0; r < 4; r++) acc[mt][nt][r] = 0.f;

    auto compute_stage = [&](const __half* stage) {
        const __half* As = stage;
        const __half* Bs = stage + A_HALves;
#pragma unroll
        for (int ks = 0; ks < 4; ks++) {            // 4 k16-steps per 64-K stage
            uint32_t af[4][4];
#pragma unroll
            for (int mt = 0; mt < 4; mt++) {
                const __half* pa = As + (wm * 64 + mt * 16 + gid) * TST + ks * 16 + tig * 4;
                const uint2 lo = *(const uint2*)pa;            // a0 (k 2t,2t+1), a2 (k 2t+8,2t+9)
                const uint2 hi = *(const uint2*)(pa + 8 * TST);// a1, a3 (row+8)
                af[mt][0] = lo.x; af[mt][1] = hi.x;
                af[mt][2] = lo.y; af[mt][3] = hi.y;
            }
            uint32_t bf[8][2];
#pragma unroll
            for (int nt = 0; nt < 8; nt++) {
                const __half* pb = Bs + (wn * 64 + nt * 8 + gid) * TST + ks * 16 + tig * 4;
                const uint2 b = *(const uint2*)pb;
                bf[nt][0] = b.x; bf[nt][1] = b.y;
            }
#pragma unroll
            for (int mt = 0; mt < 4; mt++)
#pragma unroll
                for (int nt = 0; nt < 8; nt++)
                    mma_f16(acc[mt][nt], af[mt], bf[nt]);
        }
    };

    const int niter = K / GKC;                 // 16 or 64: always even
    const uint32_t sb0 = smem_base;
    const uint32_t sb1 = smem_base + STAGE_HALVES * 2;
    const __half* st0 = smh;
    const __half* st1 = smh + STAGE_HALVES;

    issue_stage(0, sb0);
    for (int i = 0; i < niter; i += 2) {
        CP_WAIT0();
        __syncthreads();
        if (i + 1 < niter) issue_stage(i + 1, sb1);
        compute_stage(st0);
        CP_WAIT0();
        __syncthreads();
        if (i + 2 < niter) issue_stage(i + 2, sb0);
        compute_stage(st1);
    }

#pragma unroll
    for (int mt = 0; mt < 4; mt++) {
        const int r = m0 + wm * 64 + mt * 16 + gid;
#pragma unroll
        for (int nt = 0; nt < 8; nt++) {
            const int c = n0 + wn * 64 + nt * 8 + tig * 2;
            const float bx = bias[c], by = bias[c + 1];
            float2 o0, o1;
            o0.x = acc[mt][nt][0] + bx; o0.y = acc[mt][nt][1] + by;
            o1.x = acc[mt][nt][2] + bx; o1.y = acc[mt][nt][3] + by;
            if (RND) {   // feeds tf32 attention: round like before
                o0.x = rnd_tf32(o0.x); o0.y = rnd_tf32(o0.y);
                o1.x = rnd_tf32(o1.x); o1.y = rnd_tf32(o1.y);
            }
            *(float2*)(C + (size_t)r * N + c) = o0;
            *(float2*)(C + (size_t)(r + 8) * N + c) = o1;
        }
    }
}

// ===========================================================================
// Tensor-core flash attention (tf32 mma.sync).  Q/K/V fp32, NATURAL layout.
// Output: fp16 with perm16 columns (A operand of the fp16 out-proj GEMM).
// Grid (L/64, H, B), 128 threads (4 warps).
// ===========================================================================
#define QK_ST 68
#define V_ST  72
#define ATTN_SMEM ((2 * 64 * QK_ST + 64 * V_ST) * 4)   // 53248 bytes

__global__ __launch_bounds__(128) void attn_tc(
    const float* __restrict__ Q, const float* __restrict__ K,
    const float* __restrict__ V, __half* __restrict__ O)
{
    extern __shared__ float sm[];
    float* Qs = sm;                        // [64][QK_ST]
    float* Ks = Qs + 64 * QK_ST;           // [64][QK_ST]
    float* Vs = Ks + 64 * QK_ST;           // [64][V_ST]
    float* Ps = Qs;                        // alias (Q is register-resident in loop)

    const int tid  = threadIdx.x;
    const int wid  = tid >> 5;
    const int lane = tid & 31;
    const int gid  = lane >> 2;
    const int tig  = lane & 3;
    const int q0 = blockIdx.x * 64;
    const int h  = blockIdx.y;
    const int b  = blockIdx.z;

    const float* Qg = Q + ((size_t)b * Lq + q0) * DHK + h * DK;
    const float* Kg = K + ((size_t)b * Sk) * DHK + h * DK;
    const float* Vg = V + ((size_t)b * Sk) * DHK + h * DK;

    for (int g = tid; g < 64 * 16; g += 128) {
        const int r = g >> 4, e4 = g & 15;
        float4 v = *(const float4*)(Qg + (size_t)r * DHK + e4 * 4);
        *(float4*)&Qs[r * QK_ST + e4 * 4] = v;
    }
    __syncthreads();

    const int r0 = wid * 16 + gid;
    uint32_t qf[8][4];
#pragma unroll
    for (int k0 = 0; k0 < 8; k0++) {
        qf[k0][0] = __float_as_uint(Qs[r0 * QK_ST + k0 * 8 + tig] * 0.125f);
        qf[k0][1] = __float_as_uint(Qs[(r0 + 8) * QK_ST + k0 * 8 + tig] * 0.125f);
        qf[k0][2] = __float_as_uint(Qs[r0 * QK_ST + k0 * 8 + tig + 4] * 0.125f);
        qf[k0][3] = __float_as_uint(Qs[(r0 + 8) * QK_ST + k0 * 8 + tig + 4] * 0.125f);
    }

    float m0 = -INFINITY, m1 = -INFINITY, l0 = 0.f, l1 = 0.f;
    float acc[8][4];
#pragma unroll
    for (int nt = 0; nt < 8; nt++)
#pragma unroll
        for (int r = 0; r < 4; r++) acc[nt][r] = 0.f;

    for (int s0 = 0; s0 < Sk; s0 += 64) {
        __syncthreads();
        for (int g = tid; g < 64 * 16; g += 128) {
            const int r = g >> 4, e4 = g & 15;
            float4 kv = *(const float4*)(Kg + (size_t)(s0 + r) * DHK + e4 * 4);
            *(float4*)&Ks[r * QK_ST + e4 * 4] = kv;
            float4 vv = *(const float4*)(Vg + (size_t)(s0 + r) * DHK + e4 * 4);
            *(float4*)&Vs[r * V_ST + e4 * 4] = vv;
        }
        __syncthreads();

        float sc[8][4];
#pragma unroll
        for (int nt = 0; nt < 8; nt++)
#pragma unroll
            for (int r = 0; r < 4; r++) sc[nt][r] = 0.f;
#pragma unroll
        for (int k0 = 0; k0 < 8; k0++) {
#pragma unroll
            for (int nt = 0; nt < 8; nt++) {
                const uint32_t* pk =
                    (const uint32_t*)Ks + (nt * 8 + gid) * QK_ST + k0 * 8 + tig;
                uint32_t bf[2] = {pk[0], pk[4]};
                mma_tf32(sc[nt], qf[k0], bf);
            }
        }

        float mx0 = -INFINITY, mx1 = -INFINITY;
#pragma unroll
        for (int nt = 0; nt < 8; nt++) {
            mx0 = fmaxf(mx0, fmaxf(sc[nt][0], sc[nt][1]));
            mx1 = fmaxf(mx1, fmaxf(sc[nt][2], sc[nt][3]));
        }
        mx0 = fmaxf(mx0, __shfl_xor_sync(0xffffffffu, mx0, 1));
        mx0 = fmaxf(mx0, __shfl_xor_sync(0xffffffffu, mx0, 2));
        mx1 = fmaxf(mx1, __shfl_xor_sync(0xffffffffu, mx1, 1));
        mx1 = fmaxf(mx1, __shfl_xor_sync(0xffffffffu, mx1, 2));
        const float mn0 = fmaxf(m0, mx0), mn1 = fmaxf(m1, mx1);
        const float f0 = __expf(m0 - mn0), f1 = __expf(m1 - mn1);
        float sum0 = 0.f, sum1 = 0.f;
#pragma unroll
        for (int nt = 0; nt < 8; nt++) {
            sc[nt][0] = __expf(sc[nt][0] - mn0);
            sc[nt][1] = __expf(sc[nt][1] - mn0);
            sc[nt][2] = __expf(sc[nt][2] - mn1);
            sc[nt][3] = __expf(sc[nt][3] - mn1);
            sum0 += sc[nt][0] + sc[nt][1];
            sum1 += sc[nt][2] + sc[nt][3];
        }
        sum0 += __shfl_xor_sync(0xffffffffu, sum0, 1);
        sum0 += __shfl_xor_sync(0xffffffffu, sum0, 2);
        sum1 += __shfl_xor_sync(0xffffffffu, sum1, 1);
        sum1 += __shfl_xor_sync(0xffffffffu, sum1, 2);
        l0 = l0 * f0 + sum0;  m0 = mn0;
        l1 = l1 * f1 + sum1;  m1 = mn1;

#pragma unroll
        for (int nt = 0; nt < 8; nt++) {
            acc[nt][0] *= f0; acc[nt][1] *= f0;
            acc[nt][2] *= f1; acc[nt][3] *= f1;
        }

#pragma unroll
        for (int nt = 0; nt < 8; nt++) {
            float2 p0, p1;
            p0.x = rnd_tf32(sc[nt][0]); p0.y = rnd_tf32(sc[nt][1]);
            p1.x = rnd_tf32(sc[nt][2]); p1.y = rnd_tf32(sc[nt][3]);
            *(float2*)&Ps[r0 * QK_ST + nt * 8 + tig * 2] = p0;
            *(float2*)&Ps[(r0 + 8) * QK_ST + nt * 8 + tig * 2] = p1;
        }
        __syncwarp();

#pragma unroll
        for (int k0 = 0; k0 < 8; k0++) {
            const uint32_t* pp = (const uint32_t*)Ps + r0 * QK_ST + k0 * 8 + tig;
            uint32_t af[4];
            af[0] = pp[0];
            af[1] = pp[8 * QK_ST];
            af[2] = pp[4];
            af[3] = pp[8 * QK_ST + 4];
#pragma unroll
            for (int nt = 0; nt < 8; nt++) {
                const uint32_t* pv =
                    (const uint32_t*)Vs + (k0 * 8 + tig) * V_ST + nt * 8 + gid;
                uint32_t bf[2] = {pv[0], pv[4 * V_ST]};
                mma_tf32(acc[nt], af, bf);
            }
        }
    }

    // Epilogue: normalize, convert fp16, store with perm16 columns (half2:
    // even-k pairs map to adjacent permuted positions).
    const float inv0 = 1.f / l0, inv1 = 1.f / l1;
    __half* Og = O + ((size_t)b * Lq + q0 + r0) * DHK + h * DK;
#pragma unroll
    for (int nt = 0; nt < 8; nt++) {
        const int c = nt * 8 + tig * 2;
        const int cp = (c & ~15) + perm16(c & 15);
        *(__half2*)(Og + cp) = __floats2half2_rn(acc[nt][0] * inv0, acc[nt][1] * inv0);
        *(__half2*)(Og + (size_t)8 * DHK + cp) =
            __floats2half2_rn(acc[nt][2] * inv1, acc[nt][3] * inv1);
    }
}

// ===========================================================================
// Launch
// ===========================================================================
extern "C" void kernel_launch(void* const* d_in, const int* in_sizes, int n_in,
                              void* d_out, int out_size)
{
    const float* target = (const float*)d_in[0];
    const float* source = (const float*)d_in[1];
    const float* Wq = (const float*)d_in[2];
    const float* bq = (const float*)d_in[3];
    const float* Wk = (const float*)d_in[4];
    const float* bk = (const float*)d_in[5];
    const float* Wv = (const float*)d_in[6];
    const float* bv = (const float*)d_in[7];
    const float* Wo = (const float*)d_in[8];
    const float* bo = (const float*)d_in[9];
    float* out = (float*)d_out;

    float*  Qb; cudaGetSymbolAddress((void**)&Qb, g_Q);
    float*  Kb; cudaGetSymbolAddress((void**)&Kb, g_K);
    float*  Vb; cudaGetSymbolAddress((void**)&Vb, g_V);
    __half* Hb; cudaGetSymbolAddress((void**)&Hb, g_H);
    __half* WT; cudaGetSymbolAddress((void**)&WT, g_WT);
    __half* Sr; cudaGetSymbolAddress((void**)&Sr, g_Sr);

    const int ML = Bz * Lq;   // 16384
    const int MS = Bz * Sk;   // 8192

    cudaFuncSetAttribute(gemm_mma<0>, cudaFuncAttributeMaxDynamicSharedMemorySize, SMEM_GEMM);
    cudaFuncSetAttribute(gemm_mma<1>, cudaFuncAttributeMaxDynamicSharedMemorySize, SMEM_GEMM);
    cudaFuncSetAttribute(attn_tc, cudaFuncAttributeMaxDynamicSharedMemorySize, ATTN_SMEM);

    // fp16 + perm16 inputs once
    {
        const int nt4 = ML * DM / 4;        // 4M
        round_perm_k<<<nt4 / 256, 256>>>((const float4*)target, Hb, nt4);
        const int ns4 = MS * DLLM / 4;      // 8M
        round_perm_k<<<ns4 / 256, 256>>>((const float4*)source, Sr, ns4);
    }

    // Q = h(target) @ Wq + bq   (fp32 out, tf32-rounded for attention)
    transpose_k<<<dim3(DHK / 32, DM / 32), dim3(32, 8)>>>(Wq, WT, DM, DHK);
    gemm_mma<1><<<dim3(DHK / GN, ML / GM), 128, SMEM_GEMM>>>(Hb, WT, bq, Qb, DM, DHK);

    // K = h(source) @ Wk + bk
    transpose_k<<<dim3(DHK / 32, DLLM / 32), dim3(32, 8)>>>(Wk, WT, DLLM, DHK);
    gemm_mma<1><<<dim3(DHK / GN, MS / GM), 128, SMEM_GEMM>>>(Sr, WT, bk, Kb, DLLM, DHK);

    // V = h(source) @ Wv + bv
    transpose_k<<<dim3(DHK / 32, DLLM / 32), dim3(32, 8)>>>(Wv, WT, DLLM, DHK);
    gemm_mma<1><<<dim3(DHK / GN, MS / GM), 128, SMEM_GEMM>>>(Sr, WT, bv, Vb, DLLM, DHK);

    // Attention (reads fp32 Q/K/V; writes fp16+perm16 into Hb — safe: the only
    // reader of Hb's previous contents, the Q-proj GEMM, already ran)
    attn_tc<<<dim3(Lq / 64, NH, Bz), 128, ATTN_SMEM>>>(Qb, Kb, Vb, Hb);

    // out = attn @ Wo + bo  (final output fp32, not rounded)
    transpose_k<<<dim3(DLLM / 32, DHK / 32), dim3(32, 8)>>>(Wo, WT, DHK, DLLM);
    gemm_mma<0><<<dim3(DLLM / GN, ML / GM), 128, SMEM_GEMM>>>(Hb, WT, bo, out, DHK, DLLM);
}

// round 13
// speedup vs baseline: 1.7145x; 1.0579x over previous
#include <cuda_runtime.h>
#include <cuda_fp16.h>
#include <cstdint>
#include <math.h>

#define Bz 8
#define Lq 2048
#define Sk 1024
#define DM 1024
#define DLLM 4096
#define NH 16
#define DK 64
#define DHK 1024

// Scratch (allocation-free rule: __device__ globals)
__device__ __half g_Qh[(size_t)Bz * Lq * DHK];    // 32 MB fp16 perm16 (Q)
__device__ __half g_Kh[(size_t)Bz * Sk * DHK];    // 16 MB fp16 perm16 (K)
__device__ __half g_Vh[(size_t)Bz * Sk * DHK];    // 16 MB fp16 natural (V)
__device__ __half g_H[(size_t)Bz * Lq * DHK];     // 32 MB fp16: target, then attn out
__device__ __half g_WT[(size_t)DLLM * DHK];       // 8 MB fp16 transposed weight
__device__ __half g_Sr[(size_t)Bz * Sk * DLLM];   // 64 MB fp16 source

// ===========================================================================
// Helpers
// ===========================================================================
__device__ __forceinline__ void cp16(uint32_t dst, const void* src) {
    asm volatile("cp.async.cg.shared.global [%0], [%1], 16;" :: "r"(dst), "l"(src));
}
#define CP_COMMIT() asm volatile("cp.async.commit_group;" ::: "memory")
#define CP_WAIT0()  asm volatile("cp.async.wait_group 0;" ::: "memory")

__device__ __forceinline__ uint32_t smem_u32(const void* p) {
    uint32_t a;
    asm("{ .reg .u64 t; cvta.to.shared.u64 t, %1; cvt.u32.u64 %0, t; }" : "=r"(a) : "l"(p));
    return a;
}
// fp16 K-permutation within groups of 16: position of original index k.
// Order [0,1,8,9, 2,3,10,11, 4,5,12,13, 6,7,14,15]: thread t's LDS.64 at
// halves 4t..4t+3 holds original k = 2t, 2t+1, 2t+8, 2t+9.
// Even pairs (k, k+1) stay adjacent.
__device__ __forceinline__ int perm16(int k) {
    return (k < 8) ? ((k >> 1) * 4 + (k & 1)) : (((k - 8) >> 1) * 4 + 2 + (k & 1));
}

__device__ __forceinline__ void mma_f16(float c[4], const uint32_t a[4], const uint32_t b[2]) {
    asm volatile(
        "mma.sync.aligned.m16n8k16.row.col.f32.f16.f16.f32 "
        "{%0,%1,%2,%3}, {%4,%5,%6,%7}, {%8,%9}, {%0,%1,%2,%3};"
        : "+f"(c[0]), "+f"(c[1]), "+f"(c[2]), "+f"(c[3])
        : "r"(a[0]), "r"(a[1]), "r"(a[2]), "r"(a[3]), "r"(b[0]), "r"(b[1]));
}

// ===========================================================================
// fp32 -> fp16 with perm16 on (flat & 15).  Row strides divisible by 16.
// ===========================================================================
__global__ __launch_bounds__(256) void round_perm_k(
    const float4* __restrict__ in, __half* __restrict__ out, int n4)
{
    const int i = blockIdx.x * 256 + threadIdx.x;
    if (i < n4) {
        float4 v = in[i];
        const size_t f = (size_t)i * 4;
        const int k = (int)(f & 15);            // even; k and k+2 in same 16-group
        __half* base = out + (f - k);
        *(__half2*)(base + perm16(k))     = __floats2half2_rn(v.x, v.y);
        *(__half2*)(base + perm16(k + 2)) = __floats2half2_rn(v.z, v.w);
    }
}

// ===========================================================================
// Weight transpose -> fp16 with perm16 on output column (= GEMM K-dim):
// in [R,C] row-major -> out [C,R] fp16.
// ===========================================================================
__global__ __launch_bounds__(256) void transpose_k(
    const float* __restrict__ in, __half* __restrict__ out, int R, int C)
{
    __shared__ float tile[32][33];
    const int c0 = blockIdx.x * 32, r0 = blockIdx.y * 32;
    const int x = threadIdx.x, y = threadIdx.y;  // 32 x 8
#pragma unroll
    for (int i = 0; i < 32; i += 8)
        tile[y + i][x] = in[(size_t)(r0 + y + i) * C + c0 + x];
    __syncthreads();
    const int xp = (x & ~15) + perm16(x & 15);
#pragma unroll
    for (int i = 0; i < 32; i += 8)
        out[(size_t)(c0 + y + i) * R + r0 + xp] = __float2half_rn(tile[x][y + i]);
}

// ===========================================================================
// fp16 mma.sync GEMM: C[M,N] = A[M,K] @ Bt[N,K]^T + bias  (fp32 accum)
// K pre-permuted (perm16) -> all fragment loads are LDS.64.
// Block tile 128x128x64, 4 warps (2Mx2N), warp tile 64x64, m16n8k16,
// double-buffered cp.async, mainloop unrolled x2. 2 CTAs/SM (80KB smem).
// Epilogue MODE: 0 = fp32 (final out), 1 = fp16 perm16 (Q/K), 2 = fp16 natural (V).
// ===========================================================================
#define GM 128
#define GN 128
#define GKC 64
#define TST 80                                       // halves; 160B row: LDS.64 conflict-free
#define A_HALVES (GM * TST)                          // 10240 halves
#define STAGE_HALVES (2 * GM * TST)
#define SMEM_GEMM (2 * STAGE_HALVES * 2)             // 81920 bytes

template <int MODE>
__global__ __launch_bounds__(128, 2) void gemm_mma(
    const __half* __restrict__ A, const __half* __restrict__ Bt,
    const float* __restrict__ bias, void* __restrict__ Cv,
    int K, int N)
{
    extern __shared__ __half smh[];
    const uint32_t smem_base = smem_u32(smh);
    const int tid  = threadIdx.x;
    const int wid  = tid >> 5;
    const int lane = tid & 31;
    const int wm   = wid >> 1;
    const int wn   = wid & 1;
    const int gid  = lane >> 2;
    const int tig  = lane & 3;
    const int m0 = blockIdx.y * GM;
    const int n0 = blockIdx.x * GN;

    const __half* Ag = A + (size_t)m0 * K;
    const __half* Bg = Bt + (size_t)n0 * K;

    auto issue_stage = [&](int i, uint32_t sb) {
        const int k0 = i * GKC;
#pragma unroll
        for (int u = 0; u < 8; u++) {
            const int g = tid + u * 128;
            const int row = g >> 3, c8 = g & 7;
            cp16(sb + (uint32_t)(row * TST * 2 + c8 * 16),
                 Ag + (size_t)row * K + k0 + c8 * 8);
        }
        const uint32_t sbB = sb + A_HALVES * 2;
#pragma unroll
        for (int u = 0; u < 8; u++) {
            const int g = tid + u * 128;
            const int row = g >> 3, c8 = g & 7;
            cp16(sbB + (uint32_t)(row * TST * 2 + c8 * 16),
                 Bg + (size_t)row * K + k0 + c8 * 8);
        }
        CP_COMMIT();
    };

    float acc[4][8][4];
#pragma unroll
    for (int mt = 0; mt < 4; mt++)
#pragma unroll
        for (int nt = 0; nt < 8; nt++)
#pragma unroll
            for (int r = 0; r < 4; r++) acc[mt][nt][r] = 0.f;

    auto compute_stage = [&](const __half* stage) {
        const __half* As = stage;
        const __half* Bs = stage + A_HALVES;
#pragma unroll
        for (int ks = 0; ks < 4; ks++) {
            uint32_t af[4][4];
#pragma unroll
            for (int mt = 0; mt < 4; mt++) {
                const __half* pa = As + (wm * 64 + mt * 16 + gid) * TST + ks * 16 + tig * 4;
                const uint2 lo = *(const uint2*)pa;
                const uint2 hi = *(const uint2*)(pa + 8 * TST);
                af[mt][0] = lo.x; af[mt][1] = hi.x;
                af[mt][2] = lo.y; af[mt][3] = hi.y;
            }
            uint32_t bf[8][2];
#pragma unroll
            for (int nt = 0; nt < 8; nt++) {
                const __half* pb = Bs + (wn * 64 + nt * 8 + gid) * TST + ks * 16 + tig * 4;
                const uint2 b = *(const uint2*)pb;
                bf[nt][0] = b.x; bf[nt][1] = b.y;
            }
#pragma unroll
            for (int mt = 0; mt < 4; mt++)
#pragma unroll
                for (int nt = 0; nt < 8; nt++)
                    mma_f16(acc[mt][nt], af[mt], bf[nt]);
        }
    };

    const int niter = K / GKC;                 // 16 or 64: always even
    const uint32_t sb0 = smem_base;
    const uint32_t sb1 = smem_base + STAGE_HALVES * 2;
    const __half* st0 = smh;
    const __half* st1 = smh + STAGE_HALVES;

    issue_stage(0, sb0);
    for (int i = 0; i < niter; i += 2) {
        CP_WAIT0();
        __syncthreads();
        if (i + 1 < niter) issue_stage(i + 1, sb1);
        compute_stage(st0);
        CP_WAIT0();
        __syncthreads();
        if (i + 2 < niter) issue_stage(i + 2, sb0);
        compute_stage(st1);
    }

#pragma unroll
    for (int mt = 0; mt < 4; mt++) {
        const int r = m0 + wm * 64 + mt * 16 + gid;
#pragma unroll
        for (int nt = 0; nt < 8; nt++) {
            const int c = n0 + wn * 64 + nt * 8 + tig * 2;
            const float bx = bias[c], by = bias[c + 1];
            const float v00 = acc[mt][nt][0] + bx, v01 = acc[mt][nt][1] + by;
            const float v10 = acc[mt][nt][2] + bx, v11 = acc[mt][nt][3] + by;
            if (MODE == 0) {
                float* C = (float*)Cv;
                *(float2*)(C + (size_t)r * N + c) = make_float2(v00, v01);
                *(float2*)(C + (size_t)(r + 8) * N + c) = make_float2(v10, v11);
            } else if (MODE == 1) {
                __half* C = (__half*)Cv;
                const int cp = (c & ~15) + perm16(c & 15);
                *(__half2*)(C + (size_t)r * N + cp) = __floats2half2_rn(v00, v01);
                *(__half2*)(C + (size_t)(r + 8) * N + cp) = __floats2half2_rn(v10, v11);
            } else {
                __half* C = (__half*)Cv;
                *(__half2*)(C + (size_t)r * N + c) = __floats2half2_rn(v00, v01);
                *(__half2*)(C + (size_t)(r + 8) * N + c) = __floats2half2_rn(v10, v11);
            }
        }
    }
}

// ===========================================================================
// fp16 tensor-core flash attention (m16n8k16, fp32 accum).
// Q/K fp16 perm16-along-E; V fp16 natural (transposed+perm in-kernel).
// Output fp16 perm16 (A operand of out-proj). Grid (L/64, H, B), 128 thr.
// ===========================================================================
#define AST 80                                 // halves; 160B stride, conflict-free
#define ATTN_SMEM (3 * 64 * AST * 2)           // 30720 bytes

__global__ __launch_bounds__(128) void attn_tc(
    const __half* __restrict__ Q, const __half* __restrict__ K,
    const __half* __restrict__ V, __half* __restrict__ O)
{
    extern __shared__ __half smh[];
    __half* Qs = smh;                  // [64 q][AST e-perm]
    __half* Ks = Qs + 64 * AST;        // [64 s][AST e-perm]
    __half* Vt = Ks + 64 * AST;        // [64 e][AST s-perm]
    __half* Ps = Qs;                   // alias (Q fragments register-resident)

    const int tid  = threadIdx.x;
    const int wid  = tid >> 5;
    const int lane = tid & 31;
    const int gid  = lane >> 2;
    const int tig  = lane & 3;
    const int q0 = blockIdx.x * 64;
    const int h  = blockIdx.y;
    const int b  = blockIdx.z;

    const __half* Qg = Q + ((size_t)b * Lq + q0) * DHK + h * DK;
    const __half* Kg = K + ((size_t)b * Sk) * DHK + h * DK;
    const __half* Vg = V + ((size_t)b * Sk) * DHK + h * DK;

    // Load Q tile: 64 rows x 64 halves = 512 granules of 16B, 4/thread
    for (int g = tid; g < 512; g += 128) {
        const int r = g >> 3, c8 = g & 7;
        *(uint4*)&Qs[r * AST + c8 * 8] = *(const uint4*)(Qg + (size_t)r * DHK + c8 * 8);
    }
    __syncthreads();

    // Q fragments to registers (4 k16-steps over E=64)
    const int r0 = wid * 16 + gid;
    uint32_t qf[4][4];
#pragma unroll
    for (int ks = 0; ks < 4; ks++) {
        const uint2 lo = *(const uint2*)(Qs + r0 * AST + ks * 16 + tig * 4);
        const uint2 hi = *(const uint2*)(Qs + (r0 + 8) * AST + ks * 16 + tig * 4);
        qf[ks][0] = lo.x; qf[ks][1] = hi.x;
        qf[ks][2] = lo.y; qf[ks][3] = hi.y;
    }

    float m0 = -INFINITY, m1 = -INFINITY, l0 = 0.f, l1 = 0.f;
    float acc[8][4];
#pragma unroll
    for (int nt = 0; nt < 8; nt++)
#pragma unroll
        for (int r = 0; r < 4; r++) acc[nt][r] = 0.f;

    for (int s0 = 0; s0 < Sk; s0 += 64) {
        __syncthreads();   // prior-iter Ks/Vt/Ps reads done (and Q frag loads, iter 0)

        // K tile (already perm16 along E): plain 16B copies
        for (int g = tid; g < 512; g += 128) {
            const int r = g >> 3, c8 = g & 7;
            *(uint4*)&Ks[r * AST + c8 * 8] =
                *(const uint4*)(Kg + (size_t)(s0 + r) * DHK + c8 * 8);
        }
        // V transpose: Vt[e][s_perm]. Unit u: sp = u&31 (s-pair), ec = u>>5.
        // Even s-pairs map to adjacent perm16 slots -> half2 stores, and the
        // (sp = lane) mapping makes the STS.32 banks all distinct.
        for (int u = tid; u < 256; u += 128) {
            const int sp = u & 31, e8 = (u >> 5) * 8;
            const int s = 2 * sp;
            const uint4 va = *(const uint4*)(Vg + (size_t)(s0 + s) * DHK + e8);
            const uint4 vb = *(const uint4*)(Vg + (size_t)(s0 + s + 1) * DHK + e8);
            const __half* ha = (const __half*)&va;
            const __half* hb = (const __half*)&vb;
            const int spos = (s & ~15) + perm16(s & 15);
#pragma unroll
            for (int i = 0; i < 8; i++)
                *(__half2*)&Vt[(e8 + i) * AST + spos] = __halves2half2(ha[i], hb[i]);
        }
        __syncthreads();

        // Scores: QK^T (4 k16-steps), then scale by 1/8 in fp32
        float sc[8][4];
#pragma unroll
        for (int nt = 0; nt < 8; nt++)
#pragma unroll
            for (int r = 0; r < 4; r++) sc[nt][r] = 0.f;
#pragma unroll
        for (int ks = 0; ks < 4; ks++) {
#pragma unroll
            for (int nt = 0; nt < 8; nt++) {
                const uint2 bk = *(const uint2*)(Ks + (nt * 8 + gid) * AST + ks * 16 + tig * 4);
                uint32_t bf[2] = {bk.x, bk.y};
                mma_f16(sc[nt], qf[ks], bf);
            }
        }
#pragma unroll
        for (int nt = 0; nt < 8; nt++)
#pragma unroll
            for (int r = 0; r < 4; r++) sc[nt][r] *= 0.125f;

        // Online softmax (rows r0, r0+8; spread over 4 tig lanes)
        float mx0 = -INFINITY, mx1 = -INFINITY;
#pragma unroll
        for (int nt = 0; nt < 8; nt++) {
            mx0 = fmaxf(mx0, fmaxf(sc[nt][0], sc[nt][1]));
            mx1 = fmaxf(mx1, fmaxf(sc[nt][2], sc[nt][3]));
        }
        mx0 = fmaxf(mx0, __shfl_xor_sync(0xffffffffu, mx0, 1));
        mx0 = fmaxf(mx0, __shfl_xor_sync(0xffffffffu, mx0, 2));
        mx1 = fmaxf(mx1, __shfl_xor_sync(0xffffffffu, mx1, 1));
        mx1 = fmaxf(mx1, __shfl_xor_sync(0xffffffffu, mx1, 2));
        const float mn0 = fmaxf(m0, mx0), mn1 = fmaxf(m1, mx1);
        const float f0 = __expf(m0 - mn0), f1 = __expf(m1 - mn1);
        float sum0 = 0.f, sum1 = 0.f;
#pragma unroll
        for (int nt = 0; nt < 8; nt++) {
            sc[nt][0] = __expf(sc[nt][0] - mn0);
            sc[nt][1] = __expf(sc[nt][1] - mn0);
            sc[nt][2] = __expf(sc[nt][2] - mn1);
            sc[nt][3] = __expf(sc[nt][3] - mn1);
            sum0 += sc[nt][0] + sc[nt][1];
            sum1 += sc[nt][2] + sc[nt][3];
        }
        sum0 += __shfl_xor_sync(0xffffffffu, sum0, 1);
        sum0 += __shfl_xor_sync(0xffffffffu, sum0, 2);
        sum1 += __shfl_xor_sync(0xffffffffu, sum1, 1);
        sum1 += __shfl_xor_sync(0xffffffffu, sum1, 2);
        l0 = l0 * f0 + sum0;  m0 = mn0;
        l1 = l1 * f1 + sum1;  m1 = mn1;

#pragma unroll
        for (int nt = 0; nt < 8; nt++) {
            acc[nt][0] *= f0; acc[nt][1] *= f0;
            acc[nt][2] *= f1; acc[nt][3] *= f1;
        }

        // P -> fp16 perm16 (cols = s), warp-private rows of Ps
#pragma unroll
        for (int nt = 0; nt < 8; nt++) {
            const int c = nt * 8 + tig * 2;
            const int cp = (c & ~15) + perm16(c & 15);
            *(__half2*)&Ps[r0 * AST + cp] = __floats2half2_rn(sc[nt][0], sc[nt][1]);
            *(__half2*)&Ps[(r0 + 8) * AST + cp] = __floats2half2_rn(sc[nt][2], sc[nt][3]);
        }
        __syncwarp();

        // PV: acc[e-tile] += P[q][s] @ Vt[e][s]  (4 k16-steps over s)
#pragma unroll
        for (int ks = 0; ks < 4; ks++) {
            const uint2 lo = *(const uint2*)(Ps + r0 * AST + ks * 16 + tig * 4);
            const uint2 hi = *(const uint2*)(Ps + (r0 + 8) * AST + ks * 16 + tig * 4);
            uint32_t af[4] = {lo.x, hi.x, lo.y, hi.y};
#pragma unroll
            for (int nt = 0; nt < 8; nt++) {
                const uint2 bv = *(const uint2*)(Vt + (nt * 8 + gid) * AST + ks * 16 + tig * 4);
                uint32_t bf[2] = {bv.x, bv.y};
                mma_f16(acc[nt], af, bf);
            }
        }
    }

    // Epilogue: normalize, fp16 + perm16 store (feeds out-proj A operand)
    const float inv0 = 1.f / l0, inv1 = 1.f / l1;
    __half* Og = O + ((size_t)b * Lq + q0 + r0) * DHK + h * DK;
#pragma unroll
    for (int nt = 0; nt < 8; nt++) {
        const int c = nt * 8 + tig * 2;
        const int cp = (c & ~15) + perm16(c & 15);
        *(__half2*)(Og + cp) = __floats2half2_rn(acc[nt][0] * inv0, acc[nt][1] * inv0);
        *(__half2*)(Og + (size_t)8 * DHK + cp) =
            __floats2half2_rn(acc[nt][2] * inv1, acc[nt][3] * inv1);
    }
}

// ===========================================================================
// Launch
// ===========================================================================
extern "C" void kernel_launch(void* const* d_in, const int* in_sizes, int n_in,
                              void* d_out, int out_size)
{
    const float* target = (const float*)d_in[0];
    const float* source = (const float*)d_in[1];
    const float* Wq = (const float*)d_in[2];
    const float* bq = (const float*)d_in[3];
    const float* Wk = (const float*)d_in[4];
    const float* bk = (const float*)d_in[5];
    const float* Wv = (const float*)d_in[6];
    const float* bv = (const float*)d_in[7];
    const float* Wo = (const float*)d_in[8];
    const float* bo = (const float*)d_in[9];
    float* out = (float*)d_out;

    __half* Qh; cudaGetSymbolAddress((void**)&Qh, g_Qh);
    __half* Kh; cudaGetSymbolAddress((void**)&Kh, g_Kh);
    __half* Vh; cudaGetSymbolAddress((void**)&Vh, g_Vh);
    __half* Hb; cudaGetSymbolAddress((void**)&Hb, g_H);
    __half* WT; cudaGetSymbolAddress((void**)&WT, g_WT);
    __half* Sr; cudaGetSymbolAddress((void**)&Sr, g_Sr);

    const int ML = Bz * Lq;   // 16384
    const int MS = Bz * Sk;   // 8192

    cudaFuncSetAttribute(gemm_mma<0>, cudaFuncAttributeMaxDynamicSharedMemorySize, SMEM_GEMM);
    cudaFuncSetAttribute(gemm_mma<1>, cudaFuncAttributeMaxDynamicSharedMemorySize, SMEM_GEMM);
    cudaFuncSetAttribute(gemm_mma<2>, cudaFuncAttributeMaxDynamicSharedMemorySize, SMEM_GEMM);
    cudaFuncSetAttribute(attn_tc, cudaFuncAttributeMaxDynamicSharedMemorySize, ATTN_SMEM);

    // fp16 + perm16 inputs once
    {
        const int nt4 = ML * DM / 4;        // 4M
        round_perm_k<<<nt4 / 256, 256>>>((const float4*)target, Hb, nt4);
        const int ns4 = MS * DLLM / 4;      // 8M
        round_perm_k<<<ns4 / 256, 256>>>((const float4*)source, Sr, ns4);
    }

    // Q = h(target) @ Wq + bq   -> fp16 perm16 (E = QK^T k-dim)
    transpose_k<<<dim3(DHK / 32, DM / 32), dim3(32, 8)>>>(Wq, WT, DM, DHK);
    gemm_mma<1><<<dim3(DHK / GN, ML / GM), 128, SMEM_GEMM>>>(Hb, WT, bq, Qh, DM, DHK);

    // K = h(source) @ Wk + bk   -> fp16 perm16
    transpose_k<<<dim3(DHK / 32, DLLM / 32), dim3(32, 8)>>>(Wk, WT, DLLM, DHK);
    gemm_mma<1><<<dim3(DHK / GN, MS / GM), 128, SMEM_GEMM>>>(Sr, WT, bk, Kh, DLLM, DHK);

    // V = h(source) @ Wv + bv   -> fp16 natural
    transpose_k<<<dim3(DHK / 32, DLLM / 32), dim3(32, 8)>>>(Wv, WT, DLLM, DHK);
    gemm_mma<2><<<dim3(DHK / GN, MS / GM), 128, SMEM_GEMM>>>(Sr, WT, bv, Vh, DLLM, DHK);

    // Attention (writes fp16+perm16 into Hb — safe: Q-proj, the only reader
    // of Hb's previous contents, already ran)
    attn_tc<<<dim3(Lq / 64, NH, Bz), 128, ATTN_SMEM>>>(Qh, Kh, Vh, Hb);

    // out = attn @ Wo + bo  (final output fp32)
    transpose_k<<<dim3(DLLM / 32, DHK / 32), dim3(32, 8)>>>(Wo, WT, DHK, DLLM);
    gemm_mma<0><<<dim3(DLLM / GN, ML / GM), 128, SMEM_GEMM>>>(Hb, WT, bo, out, DHK, DLLM);
}

// round 14
// speedup vs baseline: 2.0408x; 1.1903x over previous
#include <cuda_runtime.h>
#include <cuda_fp16.h>
#include <cstdint>
#include <math.h>

#define Bz 8
#define Lq 2048
#define Sk 1024
#define DM 1024
#define DLLM 4096
#define NH 16
#define DK 64
#define DHK 1024

// Scratch (allocation-free rule: __device__ globals)
__device__ __half g_Qh[(size_t)Bz * Lq * DHK];    // 32 MB fp16 perm16, pre-scaled (Q)
__device__ __half g_Kh[(size_t)Bz * Sk * DHK];    // 16 MB fp16 perm16 (K)
__device__ __half g_Vh[(size_t)Bz * Sk * DHK];    // 16 MB fp16 natural (V)
__device__ __half g_Vt[(size_t)Bz * Sk * DHK];    // 16 MB fp16 [b][h][e][s_perm]
__device__ __half g_H[(size_t)Bz * Lq * DHK];     // 32 MB fp16: target, then attn out
__device__ __half g_WT[(size_t)DLLM * DHK];       // 8 MB fp16 transposed weight
__device__ __half g_Sr[(size_t)Bz * Sk * DLLM];   // 64 MB fp16 source

// ===========================================================================
// Helpers
// ===========================================================================
__device__ __forceinline__ void cp16(uint32_t dst, const void* src) {
    asm volatile("cp.async.cg.shared.global [%0], [%1], 16;" :: "r"(dst), "l"(src));
}
#define CP_COMMIT() asm volatile("cp.async.commit_group;" ::: "memory")
#define CP_WAIT0()  asm volatile("cp.async.wait_group 0;" ::: "memory")

__device__ __forceinline__ uint32_t smem_u32(const void* p) {
    uint32_t a;
    asm("{ .reg .u64 t; cvta.to.shared.u64 t, %1; cvt.u32.u64 %0, t; }" : "=r"(a) : "l"(p));
    return a;
}
// fp16 K-permutation within groups of 16: position of original index k is
// perm16(k); order [0,1,8,9, 2,3,10,11, 4,5,12,13, 6,7,14,15].
// Thread t's LDS.64 at halves 4t..4t+3 holds original k = 2t,2t+1,2t+8,2t+9.
__device__ __forceinline__ int perm16(int k) {
    return (k < 8) ? ((k >> 1) * 4 + (k & 1)) : (((k - 8) >> 1) * 4 + 2 + (k & 1));
}
// Inverse: original index sitting at permuted position p.
__device__ __forceinline__ int iperm16(int p) {
    return ((p & 2) ? 8 : 0) + ((p >> 2) << 1) + (p & 1);
}

__device__ __forceinline__ void mma_f16(float c[4], const uint32_t a[4], const uint32_t b[2]) {
    asm volatile(
        "mma.sync.aligned.m16n8k16.row.col.f32.f16.f16.f32 "
        "{%0,%1,%2,%3}, {%4,%5,%6,%7}, {%8,%9}, {%0,%1,%2,%3};"
        : "+f"(c[0]), "+f"(c[1]), "+f"(c[2]), "+f"(c[3])
        : "r"(a[0]), "r"(a[1]), "r"(a[2]), "r"(a[3]), "r"(b[0]), "r"(b[1]));
}

// ===========================================================================
// fp32 -> fp16 with perm16 on (flat & 15).  Row strides divisible by 16.
// ===========================================================================
__global__ __launch_bounds__(256) void round_perm_k(
    const float4* __restrict__ in, __half* __restrict__ out, int n4)
{
    const int i = blockIdx.x * 256 + threadIdx.x;
    if (i < n4) {
        float4 v = in[i];
        const size_t f = (size_t)i * 4;
        const int k = (int)(f & 15);            // even; k and k+2 in same 16-group
        __half* base = out + (f - k);
        *(__half2*)(base + perm16(k))     = __floats2half2_rn(v.x, v.y);
        *(__half2*)(base + perm16(k + 2)) = __floats2half2_rn(v.z, v.w);
    }
}

// ===========================================================================
// Weight transpose -> fp16 with perm16 on output column (= GEMM K-dim):
// in [R,C] row-major -> out [C,R] fp16.
// ===========================================================================
__global__ __launch_bounds__(256) void transpose_k(
    const float* __restrict__ in, __half* __restrict__ out, int R, int C)
{
    __shared__ float tile[32][33];
    const int c0 = blockIdx.x * 32, r0 = blockIdx.y * 32;
    const int x = threadIdx.x, y = threadIdx.y;  // 32 x 8
#pragma unroll
    for (int i = 0; i < 32; i += 8)
        tile[y + i][x] = in[(size_t)(r0 + y + i) * C + c0 + x];
    __syncthreads();
    const int xp = (x & ~15) + perm16(x & 15);
#pragma unroll
    for (int i = 0; i < 32; i += 8)
        out[(size_t)(c0 + y + i) * R + r0 + xp] = __float2half_rn(tile[x][y + i]);
}

// ===========================================================================
// V transpose: Vh [b][s][h][e] -> Vt [b][h][e][s_perm16].
// Grid (Sk/64, NH, Bz), 128 threads. Reads and writes are uint4.
// ===========================================================================
__global__ __launch_bounds__(128) void vtrans(
    const __half* __restrict__ V, __half* __restrict__ Vt)
{
    __shared__ __half t[64][72];
    const int s0 = blockIdx.x * 64, h = blockIdx.y, b = blockIdx.z;
    const int tid = threadIdx.x;

    for (int g = tid; g < 512; g += 128) {
        const int r = g >> 3, c8 = g & 7;
        *(uint4*)&t[r][c8 * 8] =
            *(const uint4*)(V + ((size_t)(b * Sk + s0 + r)) * DHK + h * DK + c8 * 8);
    }
    __syncthreads();

    for (int g = tid; g < 512; g += 128) {
        const int e = g >> 3, sg = g & 7;
        const int grp = (sg >> 1) * 16, off = (sg & 1) * 8;
        __half v[8];
#pragma unroll
        for (int j = 0; j < 8; j++)
            v[j] = t[grp + iperm16(off + j)][e];
        *(uint4*)(Vt + ((size_t)(b * NH + h) * DK + e) * Sk + s0 + sg * 8) =
            *(uint4*)v;
    }
}

// ===========================================================================
// fp16 mma.sync GEMM: C[M,N] = A[M,K] @ Bt[N,K]^T + bias  (fp32 accum)
// K pre-permuted (perm16) -> all fragment loads are LDS.64.
// Block tile 128x128x64, 4 warps (2Mx2N), warp tile 64x64, m16n8k16,
// double-buffered cp.async, mainloop unrolled x2. 2 CTAs/SM (80KB smem).
// MODE: 0 = fp32 out; 1 = fp16 perm16; 2 = fp16 natural; 3 = fp16 perm16 x0.125.
// ===========================================================================
#define GM 128
#define GN 128
#define GKC 64
#define TST 80                                       // halves; 160B row: LDS.64 conflict-free
#define A_HALVES (GM * TST)                          // 10240 halves
#define STAGE_HALVES (2 * GM * TST)
#define SMEM_GEMM (2 * STAGE_HALVES * 2)             // 81920 bytes

template <int MODE>
__global__ __launch_bounds__(128, 2) void gemm_mma(
    const __half* __restrict__ A, const __half* __restrict__ Bt,
    const float* __restrict__ bias, void* __restrict__ Cv,
    int K, int N)
{
    extern __shared__ __half smh[];
    const uint32_t smem_base = smem_u32(smh);
    const int tid  = threadIdx.x;
    const int wid  = tid >> 5;
    const int lane = tid & 31;
    const int wm   = wid >> 1;
    const int wn   = wid & 1;
    const int gid  = lane >> 2;
    const int tig  = lane & 3;
    const int m0 = blockIdx.y * GM;
    const int n0 = blockIdx.x * GN;

    const __half* Ag = A + (size_t)m0 * K;
    const __half* Bg = Bt + (size_t)n0 * K;

    auto issue_stage = [&](int i, uint32_t sb) {
        const int k0 = i * GKC;
#pragma unroll
        for (int u = 0; u < 8; u++) {
            const int g = tid + u * 128;
            const int row = g >> 3, c8 = g & 7;
            cp16(sb + (uint32_t)(row * TST * 2 + c8 * 16),
                 Ag + (size_t)row * K + k0 + c8 * 8);
        }
        const uint32_t sbB = sb + A_HALVES * 2;
#pragma unroll
        for (int u = 0; u < 8; u++) {
            const int g = tid + u * 128;
            const int row = g >> 3, c8 = g & 7;
            cp16(sbB + (uint32_t)(row * TST * 2 + c8 * 16),
                 Bg + (size_t)row * K + k0 + c8 * 8);
        }
        CP_COMMIT();
    };

    float acc[4][8][4];
#pragma unroll
    for (int mt = 0; mt < 4; mt++)
#pragma unroll
        for (int nt = 0; nt < 8; nt++)
#pragma unroll
            for (int r = 0; r < 4; r++) acc[mt][nt][r] = 0.f;

    auto compute_stage = [&](const __half* stage) {
        const __half* As = stage;
        const __half* Bs = stage + A_HALVES;
#pragma unroll
        for (int ks = 0; ks < 4; ks++) {
            uint32_t af[4][4];
#pragma unroll
            for (int mt = 0; mt < 4; mt++) {
                const __half* pa = As + (wm * 64 + mt * 16 + gid) * TST + ks * 16 + tig * 4;
                const uint2 lo = *(const uint2*)pa;
                const uint2 hi = *(const uint2*)(pa + 8 * TST);
                af[mt][0] = lo.x; af[mt][1] = hi.x;
                af[mt][2] = lo.y; af[mt][3] = hi.y;
            }
            uint32_t bf[8][2];
#pragma unroll
            for (int nt = 0; nt < 8; nt++) {
                const __half* pb = Bs + (wn * 64 + nt * 8 + gid) * TST + ks * 16 + tig * 4;
                const uint2 b = *(const uint2*)pb;
                bf[nt][0] = b.x; bf[nt][1] = b.y;
            }
#pragma unroll
            for (int mt = 0; mt < 4; mt++)
#pragma unroll
                for (int nt = 0; nt < 8; nt++)
                    mma_f16(acc[mt][nt], af[mt], bf[nt]);
        }
    };

    const int niter = K / GKC;                 // 16 or 64: always even
    const uint32_t sb0 = smem_base;
    const uint32_t sb1 = smem_base + STAGE_HALVES * 2;
    const __half* st0 = smh;
    const __half* st1 = smh + STAGE_HALVES;

    issue_stage(0, sb0);
    for (int i = 0; i < niter; i += 2) {
        CP_WAIT0();
        __syncthreads();
        if (i + 1 < niter) issue_stage(i + 1, sb1);
        compute_stage(st0);
        CP_WAIT0();
        __syncthreads();
        if (i + 2 < niter) issue_stage(i + 2, sb0);
        compute_stage(st1);
    }

#pragma unroll
    for (int mt = 0; mt < 4; mt++) {
        const int r = m0 + wm * 64 + mt * 16 + gid;
#pragma unroll
        for (int nt = 0; nt < 8; nt++) {
            const int c = n0 + wn * 64 + nt * 8 + tig * 2;
            const float bx = bias[c], by = bias[c + 1];
            float v00 = acc[mt][nt][0] + bx, v01 = acc[mt][nt][1] + by;
            float v10 = acc[mt][nt][2] + bx, v11 = acc[mt][nt][3] + by;
            if (MODE == 3) { v00 *= 0.125f; v01 *= 0.125f; v10 *= 0.125f; v11 *= 0.125f; }
            if (MODE == 0) {
                float* C = (float*)Cv;
                *(float2*)(C + (size_t)r * N + c) = make_float2(v00, v01);
                *(float2*)(C + (size_t)(r + 8) * N + c) = make_float2(v10, v11);
            } else if (MODE == 1 || MODE == 3) {
                __half* C = (__half*)Cv;
                const int cp = (c & ~15) + perm16(c & 15);
                *(__half2*)(C + (size_t)r * N + cp) = __floats2half2_rn(v00, v01);
                *(__half2*)(C + (size_t)(r + 8) * N + cp) = __floats2half2_rn(v10, v11);
            } else {
                __half* C = (__half*)Cv;
                *(__half2*)(C + (size_t)r * N + c) = __floats2half2_rn(v00, v01);
                *(__half2*)(C + (size_t)(r + 8) * N + c) = __floats2half2_rn(v10, v11);
            }
        }
    }
}

// ===========================================================================
// fp16 flash attention, fully pipelined.
// Q fp16 perm16 pre-scaled; K fp16 perm16; Vt fp16 [b][h][e][s_perm].
// cp.async double-buffered K/Vt tiles. Output fp16 perm16.
// Grid (L/64, H, B), 128 threads (4 warps, 16 q-rows each).
// ===========================================================================
#define AST 80                                  // halves; 160B stride, conflict-free
#define ATTN_TILE (64 * AST)                    // 5120 halves per operand tile
#define ATTN_STAGE (2 * ATTN_TILE)              // K + V
#define ATTN_SMEM ((2 * ATTN_STAGE + ATTN_TILE) * 2)   // 51200 bytes

__global__ __launch_bounds__(128) void attn_tc(
    const __half* __restrict__ Q, const __half* __restrict__ K,
    const __half* __restrict__ Vt, __half* __restrict__ O)
{
    extern __shared__ __half smh[];
    const uint32_t smem_base = smem_u32(smh);
    __half* Ps = smh + 2 * ATTN_STAGE;      // [64 q][AST]; also Q staging

    const int tid  = threadIdx.x;
    const int wid  = tid >> 5;
    const int lane = tid & 31;
    const int gid  = lane >> 2;
    const int tig  = lane & 3;
    const int q0 = blockIdx.x * 64;
    const int h  = blockIdx.y;
    const int b  = blockIdx.z;

    const __half* Qg  = Q + ((size_t)b * Lq + q0) * DHK + h * DK;
    const __half* Kg  = K + ((size_t)b * Sk) * DHK + h * DK;
    const __half* Vtg = Vt + ((size_t)b * NH + h) * DK * Sk;

    // Stage Q through Ps region, extract register fragments (pre-scaled, perm16)
    for (int g = tid; g < 512; g += 128) {
        const int r = g >> 3, c8 = g & 7;
        *(uint4*)&Ps[r * AST + c8 * 8] = *(const uint4*)(Qg + (size_t)r * DHK + c8 * 8);
    }
    __syncthreads();
    const int r0 = wid * 16 + gid;
    uint32_t qf[4][4];
#pragma unroll
    for (int ks = 0; ks < 4; ks++) {
        const uint2 lo = *(const uint2*)(Ps + r0 * AST + ks * 16 + tig * 4);
        const uint2 hi = *(const uint2*)(Ps + (r0 + 8) * AST + ks * 16 + tig * 4);
        qf[ks][0] = lo.x; qf[ks][1] = hi.x;
        qf[ks][2] = lo.y; qf[ks][3] = hi.y;
    }

    // cp.async tile loader: K rows = s, Vt rows = e; both 64 x 128B
    auto issue_tile = [&](int t, int buf) {
        const uint32_t sb = smem_base + (uint32_t)(buf * ATTN_STAGE * 2);
        const uint32_t sv = sb + ATTN_TILE * 2;
#pragma unroll
        for (int u = 0; u < 4; u++) {
            const int g = tid + u * 128;
            const int r = g >> 3, c8 = g & 7;
            cp16(sb + (uint32_t)(r * AST * 2 + c8 * 16),
                 Kg + (size_t)(t * 64 + r) * DHK + c8 * 8);
        }
#pragma unroll
        for (int u = 0; u < 4; u++) {
            const int g = tid + u * 128;
            const int r = g >> 3, c8 = g & 7;
            cp16(sv + (uint32_t)(r * AST * 2 + c8 * 16),
                 Vtg + (size_t)r * Sk + t * 64 + c8 * 8);
        }
        CP_COMMIT();
    };

    float m0 = -INFINITY, m1 = -INFINITY, l0 = 0.f, l1 = 0.f;
    float acc[8][4];
#pragma unroll
    for (int nt = 0; nt < 8; nt++)
#pragma unroll
        for (int r = 0; r < 4; r++) acc[nt][r] = 0.f;

    issue_tile(0, 0);
    for (int t = 0; t < Sk / 64; t++) {
        CP_WAIT0();
        __syncthreads();                     // tile t visible; prior compute done
        if (t + 1 < Sk / 64) issue_tile(t + 1, (t + 1) & 1);

        const __half* Ks = smh + (t & 1) * ATTN_STAGE;
        const __half* Vs = Ks + ATTN_TILE;

        // Scores: QK^T (Q pre-scaled)
        float sc[8][4];
#pragma unroll
        for (int nt = 0; nt < 8; nt++)
#pragma unroll
            for (int r = 0; r < 4; r++) sc[nt][r] = 0.f;
#pragma unroll
        for (int ks = 0; ks < 4; ks++) {
#pragma unroll
            for (int nt = 0; nt < 8; nt++) {
                const uint2 bk = *(const uint2*)(Ks + (nt * 8 + gid) * AST + ks * 16 + tig * 4);
                uint32_t bf[2] = {bk.x, bk.y};
                mma_f16(sc[nt], qf[ks], bf);
            }
        }

        // Online softmax (rows r0, r0+8; spread over 4 tig lanes)
        float mx0 = -INFINITY, mx1 = -INFINITY;
#pragma unroll
        for (int nt = 0; nt < 8; nt++) {
            mx0 = fmaxf(mx0, fmaxf(sc[nt][0], sc[nt][1]));
            mx1 = fmaxf(mx1, fmaxf(sc[nt][2], sc[nt][3]));
        }
        mx0 = fmaxf(mx0, __shfl_xor_sync(0xffffffffu, mx0, 1));
        mx0 = fmaxf(mx0, __shfl_xor_sync(0xffffffffu, mx0, 2));
        mx1 = fmaxf(mx1, __shfl_xor_sync(0xffffffffu, mx1, 1));
        mx1 = fmaxf(mx1, __shfl_xor_sync(0xffffffffu, mx1, 2));
        const float mn0 = fmaxf(m0, mx0), mn1 = fmaxf(m1, mx1);
        const float f0 = __expf(m0 - mn0), f1 = __expf(m1 - mn1);
        float sum0 = 0.f, sum1 = 0.f;
#pragma unroll
        for (int nt = 0; nt < 8; nt++) {
            sc[nt][0] = __expf(sc[nt][0] - mn0);
            sc[nt][1] = __expf(sc[nt][1] - mn0);
            sc[nt][2] = __expf(sc[nt][2] - mn1);
            sc[nt][3] = __expf(sc[nt][3] - mn1);
            sum0 += sc[nt][0] + sc[nt][1];
            sum1 += sc[nt][2] + sc[nt][3];
        }
        sum0 += __shfl_xor_sync(0xffffffffu, sum0, 1);
        sum0 += __shfl_xor_sync(0xffffffffu, sum0, 2);
        sum1 += __shfl_xor_sync(0xffffffffu, sum1, 1);
        sum1 += __shfl_xor_sync(0xffffffffu, sum1, 2);
        l0 = l0 * f0 + sum0;  m0 = mn0;
        l1 = l1 * f1 + sum1;  m1 = mn1;

#pragma unroll
        for (int nt = 0; nt < 8; nt++) {
            acc[nt][0] *= f0; acc[nt][1] *= f0;
            acc[nt][2] *= f1; acc[nt][3] *= f1;
        }

        // P -> fp16 perm16 (cols = s), warp-private rows of Ps
#pragma unroll
        for (int nt = 0; nt < 8; nt++) {
            const int c = nt * 8 + tig * 2;
            const int cp = (c & ~15) + perm16(c & 15);
            *(__half2*)&Ps[r0 * AST + cp] = __floats2half2_rn(sc[nt][0], sc[nt][1]);
            *(__half2*)&Ps[(r0 + 8) * AST + cp] = __floats2half2_rn(sc[nt][2], sc[nt][3]);
        }
        __syncwarp();

        // PV: acc[e-tile] += P[q][s] @ Vt[e][s]
#pragma unroll
        for (int ks = 0; ks < 4; ks++) {
            const uint2 lo = *(const uint2*)(Ps + r0 * AST + ks * 16 + tig * 4);
            const uint2 hi = *(const uint2*)(Ps + (r0 + 8) * AST + ks * 16 + tig * 4);
            uint32_t af[4] = {lo.x, hi.x, lo.y, hi.y};
#pragma unroll
            for (int nt = 0; nt < 8; nt++) {
                const uint2 bv = *(const uint2*)(Vs + (nt * 8 + gid) * AST + ks * 16 + tig * 4);
                uint32_t bf[2] = {bv.x, bv.y};
                mma_f16(acc[nt], af, bf);
            }
        }
    }

    // Epilogue: normalize, fp16 + perm16 store (feeds out-proj A operand)
    const float inv0 = 1.f / l0, inv1 = 1.f / l1;
    __half* Og = O + ((size_t)b * Lq + q0 + r0) * DHK + h * DK;
#pragma unroll
    for (int nt = 0; nt < 8; nt++) {
        const int c = nt * 8 + tig * 2;
        const int cp = (c & ~15) + perm16(c & 15);
        *(__half2*)(Og + cp) = __floats2half2_rn(acc[nt][0] * inv0, acc[nt][1] * inv0);
        *(__half2*)(Og + (size_t)8 * DHK + cp) =
            __floats2half2_rn(acc[nt][2] * inv1, acc[nt][3] * inv1);
    }
}

// ===========================================================================
// Launch
// ===========================================================================
extern "C" void kernel_launch(void* const* d_in, const int* in_sizes, int n_in,
                              void* d_out, int out_size)
{
    const float* target = (const float*)d_in[0];
    const float* source = (const float*)d_in[1];
    const float* Wq = (const float*)d_in[2];
    const float* bq = (const float*)d_in[3];
    const float* Wk = (const float*)d_in[4];
    const float* bk = (const float*)d_in[5];
    const float* Wv = (const float*)d_in[6];
    const float* bv = (const float*)d_in[7];
    const float* Wo = (const float*)d_in[8];
    const float* bo = (const float*)d_in[9];
    float* out = (float*)d_out;

    __half* Qh; cudaGetSymbolAddress((void**)&Qh, g_Qh);
    __half* Kh; cudaGetSymbolAddress((void**)&Kh, g_Kh);
    __half* Vh; cudaGetSymbolAddress((void**)&Vh, g_Vh);
    __half* Vtb; cudaGetSymbolAddress((void**)&Vtb, g_Vt);
    __half* Hb; cudaGetSymbolAddress((void**)&Hb, g_H);
    __half* WT; cudaGetSymbolAddress((void**)&WT, g_WT);
    __half* Sr; cudaGetSymbolAddress((void**)&Sr, g_Sr);

    const int ML = Bz * Lq;   // 16384
    const int MS = Bz * Sk;   // 8192

    cudaFuncSetAttribute(gemm_mma<0>, cudaFuncAttributeMaxDynamicSharedMemorySize, SMEM_GEMM);
    cudaFuncSetAttribute(gemm_mma<1>, cudaFuncAttributeMaxDynamicSharedMemorySize, SMEM_GEMM);
    cudaFuncSetAttribute(gemm_mma<2>, cudaFuncAttributeMaxDynamicSharedMemorySize, SMEM_GEMM);
    cudaFuncSetAttribute(gemm_mma<3>, cudaFuncAttributeMaxDynamicSharedMemorySize, SMEM_GEMM);
    cudaFuncSetAttribute(attn_tc, cudaFuncAttributeMaxDynamicSharedMemorySize, ATTN_SMEM);

    // fp16 + perm16 inputs once
    {
        const int nt4 = ML * DM / 4;        // 4M
        round_perm_k<<<nt4 / 256, 256>>>((const float4*)target, Hb, nt4);
        const int ns4 = MS * DLLM / 4;      // 8M
        round_perm_k<<<ns4 / 256, 256>>>((const float4*)source, Sr, ns4);
    }

    // Q = h(target) @ Wq + bq  -> fp16 perm16 scaled by 0.125 (QK^T k-dim)
    transpose_k<<<dim3(DHK / 32, DM / 32), dim3(32, 8)>>>(Wq, WT, DM, DHK);
    gemm_mma<3><<<dim3(DHK / GN, ML / GM), 128, SMEM_GEMM>>>(Hb, WT, bq, Qh, DM, DHK);

    // K = h(source) @ Wk + bk  -> fp16 perm16
    transpose_k<<<dim3(DHK / 32, DLLM / 32), dim3(32, 8)>>>(Wk, WT, DLLM, DHK);
    gemm_mma<1><<<dim3(DHK / GN, MS / GM), 128, SMEM_GEMM>>>(Sr, WT, bk, Kh, DLLM, DHK);

    // V = h(source) @ Wv + bv  -> fp16 natural, then pre-transpose for PV
    transpose_k<<<dim3(DHK / 32, DLLM / 32), dim3(32, 8)>>>(Wv, WT, DLLM, DHK);
    gemm_mma<2><<<dim3(DHK / GN, MS / GM), 128, SMEM_GEMM>>>(Sr, WT, bv, Vh, DLLM, DHK);
    vtrans<<<dim3(Sk / 64, NH, Bz), 128>>>(Vh, Vtb);

    // Attention (writes fp16+perm16 into Hb — safe: Q-proj, the only reader
    // of Hb's previous contents, already ran)
    attn_tc<<<dim3(Lq / 64, NH, Bz), 128, ATTN_SMEM>>>(Qh, Kh, Vtb, Hb);

    // out = attn @ Wo + bo  (final output fp32)
    transpose_k<<<dim3(DLLM / 32, DHK / 32), dim3(32, 8)>>>(Wo, WT, DHK, DLLM);
    gemm_mma<0><<<dim3(DLLM / GN, ML / GM), 128, SMEM_GEMM>>>(Hb, WT, bo, out, DHK, DLLM);
}

// round 17
// speedup vs baseline: 2.0897x; 1.0240x over previous
#include <cuda_runtime.h>
#include <cuda_fp16.h>
#include <cstdint>
#include <math.h>

#define Bz 8
#define Lq 2048
#define Sk 1024
#define DM 1024
#define DLLM 4096
#define NH 16
#define DK 64
#define DHK 1024

// Scratch (allocation-free rule: __device__ globals)
__device__ __half g_Qh[(size_t)Bz * Lq * DHK];    // 32 MB fp16 perm16, pre-scaled (Q)
__device__ __half g_Kh[(size_t)Bz * Sk * DHK];    // 16 MB fp16 perm16 (K)
__device__ __half g_Vh[(size_t)Bz * Sk * DHK];    // 16 MB fp16 natural (V)
__device__ __half g_Vt[(size_t)Bz * Sk * DHK];    // 16 MB fp16 [b][h][e][s_perm]
__device__ __half g_H[(size_t)Bz * Lq * DHK];     // 32 MB fp16: target, then attn out
__device__ __half g_Sr[(size_t)Bz * Sk * DLLM];   // 64 MB fp16 source
__device__ __half g_WTq[(size_t)DM * DHK];        // 2 MB
__device__ __half g_WTk[(size_t)DLLM * DHK];      // 8 MB
__device__ __half g_WTv[(size_t)DLLM * DHK];      // 8 MB
__device__ __half g_WTo[(size_t)DHK * DLLM];      // 8 MB

// ===========================================================================
// Helpers
// ===========================================================================
__device__ __forceinline__ void cp16(uint32_t dst, const void* src) {
    asm volatile("cp.async.cg.shared.global [%0], [%1], 16;" :: "r"(dst), "l"(src));
}
#define CP_COMMIT() asm volatile("cp.async.commit_group;" ::: "memory")
#define CP_WAIT0()  asm volatile("cp.async.wait_group 0;" ::: "memory")

__device__ __forceinline__ uint32_t smem_u32(const void* p) {
    uint32_t a;
    asm("{ .reg .u64 t; cvta.to.shared.u64 t, %1; cvt.u32.u64 %0, t; }" : "=r"(a) : "l"(p));
    return a;
}
// fp16 K-permutation within groups of 16: position of original index k is
// perm16(k); order [0,1,8,9, 2,3,10,11, 4,5,12,13, 6,7,14,15].
// Thread t's LDS.64 at halves 4t..4t+3 holds original k = 2t,2t+1,2t+8,2t+9.
__device__ __forceinline__ int perm16(int k) {
    return (k < 8) ? ((k >> 1) * 4 + (k & 1)) : (((k - 8) >> 1) * 4 + 2 + (k & 1));
}
// Inverse: original index sitting at permuted position p.
__device__ __forceinline__ int iperm16(int p) {
    return ((p & 2) ? 8 : 0) + ((p >> 2) << 1) + (p & 1);
}

__device__ __forceinline__ void mma_f16(float c[4], const uint32_t a[4], const uint32_t b[2]) {
    asm volatile(
        "mma.sync.aligned.m16n8k16.row.col.f32.f16.f16.f32 "
        "{%0,%1,%2,%3}, {%4,%5,%6,%7}, {%8,%9}, {%0,%1,%2,%3};"
        : "+f"(c[0]), "+f"(c[1]), "+f"(c[2]), "+f"(c[3])
        : "r"(a[0]), "r"(a[1]), "r"(a[2]), "r"(a[3]), "r"(b[0]), "r"(b[1]));
}

// ===========================================================================
// Fused fp32 -> fp16 + perm16 for BOTH input tensors in one launch.
// ===========================================================================
__global__ __launch_bounds__(256) void round_perm_fused(
    const float4* __restrict__ inA, __half* __restrict__ outA, int n4A,
    const float4* __restrict__ inB, __half* __restrict__ outB, int n4B)
{
    const int i = blockIdx.x * 256 + threadIdx.x;
    const float4* in;
    __half* out;
    int idx;
    if (i < n4A)            { in = inA; out = outA; idx = i; }
    else if (i < n4A + n4B) { in = inB; out = outB; idx = i - n4A; }
    else return;

    float4 v = in[idx];
    const size_t f = (size_t)idx * 4;
    const int k = (int)(f & 15);            // even; k and k+2 in same 16-group
    __half* base = out + (f - k);
    *(__half2*)(base + perm16(k))     = __floats2half2_rn(v.x, v.y);
    *(__half2*)(base + perm16(k + 2)) = __floats2half2_rn(v.z, v.w);
}

// ===========================================================================
// Fused weight transpose: all four weights in ONE launch (1-D grid,
// range-decoded). in [R,C] row-major -> out [C,R] fp16 with perm16 on the
// output column (= GEMM K-dim).
// Tile ranges: Wq [0,1024), Wk [1024,5120), Wv [5120,9216), Wo [9216,13312).
// ===========================================================================
#define TRANS_TILES 13312

__global__ __launch_bounds__(256) void transpose_all(
    const float* __restrict__ Wq, const float* __restrict__ Wk,
    const float* __restrict__ Wv, const float* __restrict__ Wo,
    __half* __restrict__ WTq, __half* __restrict__ WTk,
    __half* __restrict__ WTv, __half* __restrict__ WTo)
{
    __shared__ float tile[32][33];
    int t = blockIdx.x;
    const float* in;
    __half* out;
    int R, C, ct, rt;
    if (t < 1024)      { in = Wq; out = WTq; R = DM;   C = DHK;  ct = t & 31;  rt = t >> 5; }
    else if (t < 5120) { t -= 1024; in = Wk; out = WTk; R = DLLM; C = DHK; ct = t & 31;  rt = t >> 5; }
    else if (t < 9216) { t -= 5120; in = Wv; out = WTv; R = DLLM; C = DHK; ct = t & 31;  rt = t >> 5; }
    else               { t -= 9216; in = Wo; out = WTo; R = DHK;  C = DLLM; ct = t & 127; rt = t >> 7; }

    const int c0 = ct * 32, r0 = rt * 32;
    const int x = threadIdx.x & 31, y = threadIdx.x >> 5;  // 32 x 8
#pragma unroll
    for (int i = 0; i < 32; i += 8)
        tile[y + i][x] = in[(size_t)(r0 + y + i) * C + c0 + x];
    __syncthreads();
    const int xp = (x & ~15) + perm16(x & 15);
#pragma unroll
    for (int i = 0; i < 32; i += 8)
        out[(size_t)(c0 + y + i) * R + r0 + xp] = __float2half_rn(tile[x][y + i]);
}

// ===========================================================================
// V transpose: Vh [b][s][h][e] -> Vt [b][h][e][s_perm16].
// Grid (Sk/64, NH, Bz), 128 threads. Reads and writes are uint4.
// ===========================================================================
__global__ __launch_bounds__(128) void vtrans(
    const __half* __restrict__ V, __half* __restrict__ Vt)
{
    __shared__ __half t[64][72];
    const int s0 = blockIdx.x * 64, h = blockIdx.y, b = blockIdx.z;
    const int tid = threadIdx.x;

    for (int g = tid; g < 512; g += 128) {
        const int r = g >> 3, c8 = g & 7;
        *(uint4*)&t[r][c8 * 8] =
            *(const uint4*)(V + ((size_t)(b * Sk + s0 + r)) * DHK + h * DK + c8 * 8);
    }
    __syncthreads();

    for (int g = tid; g < 512; g += 128) {
        const int e = g >> 3, sg = g & 7;
        const int grp = (sg >> 1) * 16, off = (sg & 1) * 8;
        __half v[8];
#pragma unroll
        for (int j = 0; j < 8; j++)
            v[j] = t[grp + iperm16(off + j)][e];
        *(uint4*)(Vt + ((size_t)(b * NH + h) * DK + e) * Sk + s0 + sg * 8) =
            *(uint4*)v;
    }
}

// ===========================================================================
// fp16 mma.sync GEMM: C[M,N] = A[M,K] @ Bt[N,K]^T + bias  (fp32 accum)
// K pre-permuted (perm16) -> all fragment loads are LDS.64.
// Block tile 128x128x64, 4 warps (2Mx2N), warp tile 64x64, m16n8k16,
// double-buffered cp.async, mainloop unrolled x2, hoisted load addressing.
// 2 CTAs/SM (80KB smem).
// MODE: 0 = fp32 out; 1 = fp16 perm16; 2 = fp16 natural; 3 = fp16 perm16 x0.125.
// ===========================================================================
#define GM 128
#define GN 128
#define GKC 64
#define TST 80                                       // halves; 160B row: LDS.64 conflict-free
#define A_HALVES (GM * TST)                          // 10240 halves
#define STAGE_HALVES (2 * GM * TST)
#define SMEM_GEMM (2 * STAGE_HALVES * 2)             // 81920 bytes

template <int MODE>
__global__ __launch_bounds__(128, 2) void gemm_mma(
    const __half* __restrict__ A, const __half* __restrict__ Bt,
    const float* __restrict__ bias, void* __restrict__ Cv,
    int K, int N)
{
    extern __shared__ __half smh[];
    const uint32_t smem_base = smem_u32(smh);
    const int tid  = threadIdx.x;
    const int wid  = tid >> 5;
    const int lane = tid & 31;
    const int wm   = wid >> 1;
    const int wn   = wid & 1;
    const int gid  = lane >> 2;
    const int tig  = lane & 3;
    const int m0 = blockIdx.y * GM;
    const int n0 = blockIdx.x * GN;

    // Hoisted per-thread load bases: row = (tid>>3) + 16u, c8 = tid&7
    const int lrow = tid >> 3;
    const int lc8  = tid & 7;
    const __half* AgT = A + (size_t)(m0 + lrow) * K + lc8 * 8;
    const __half* BgT = Bt + (size_t)(n0 + lrow) * K + lc8 * 8;
    const uint32_t soff = (uint32_t)(lrow * TST * 2 + lc8 * 16);

    auto issue_stage = [&](int i, uint32_t sb) {
        const int k0 = i * GKC;
#pragma unroll
        for (int u = 0; u < 8; u++)
            cp16(sb + soff + (uint32_t)(u * 16 * TST * 2), AgT + (size_t)u * 16 * K + k0);
        const uint32_t sbB = sb + A_HALVES * 2;
#pragma unroll
        for (int u = 0; u < 8; u++)
            cp16(sbB + soff + (uint32_t)(u * 16 * TST * 2), BgT + (size_t)u * 16 * K + k0);
        CP_COMMIT();
    };

    float acc[4][8][4];
#pragma unroll
    for (int mt = 0; mt < 4; mt++)
#pragma unroll
        for (int nt = 0; nt < 8; nt++)
#pragma unroll
            for (int r = 0; r < 4; r++) acc[mt][nt][r] = 0.f;

    auto compute_stage = [&](const __half* stage) {
        const __half* As = stage;
        const __half* Bs = stage + A_HALVES;
#pragma unroll
        for (int ks = 0; ks < 4; ks++) {
            uint32_t af[4][4];
#pragma unroll
            for (int mt = 0; mt < 4; mt++) {
                const __half* pa = As + (wm * 64 + mt * 16 + gid) * TST + ks * 16 + tig * 4;
                const uint2 lo = *(const uint2*)pa;
                const uint2 hi = *(const uint2*)(pa + 8 * TST);
                af[mt][0] = lo.x; af[mt][1] = hi.x;
                af[mt][2] = lo.y; af[mt][3] = hi.y;
            }
            uint32_t bf[8][2];
#pragma unroll
            for (int nt = 0; nt < 8; nt++) {
                const __half* pb = Bs + (wn * 64 + nt * 8 + gid) * TST + ks * 16 + tig * 4;
                const uint2 b = *(const uint2*)pb;
                bf[nt][0] = b.x; bf[nt][1] = b.y;
            }
#pragma unroll
            for (int mt = 0; mt < 4; mt++)
#pragma unroll
                for (int nt = 0; nt < 8; nt++)
                    mma_f16(acc[mt][nt], af[mt], bf[nt]);
        }
    };

    const int niter = K / GKC;                 // 16 or 64: always even
    const uint32_t sb0 = smem_base;
    const uint32_t sb1 = smem_base + STAGE_HALVES * 2;
    const __half* st0 = smh;
    const __half* st1 = smh + STAGE_HALVES;

    issue_stage(0, sb0);
    for (int i = 0; i < niter; i += 2) {
        CP_WAIT0();
        __syncthreads();
        if (i + 1 < niter) issue_stage(i + 1, sb1);
        compute_stage(st0);
        CP_WAIT0();
        __syncthreads();
        if (i + 2 < niter) issue_stage(i + 2, sb0);
        compute_stage(st1);
    }

#pragma unroll
    for (int mt = 0; mt < 4; mt++) {
        const int r = m0 + wm * 64 + mt * 16 + gid;
#pragma unroll
        for (int nt = 0; nt < 8; nt++) {
            const int c = n0 + wn * 64 + nt * 8 + tig * 2;
            const float bx = bias[c], by = bias[c + 1];
            float v00 = acc[mt][nt][0] + bx, v01 = acc[mt][nt][1] + by;
            float v10 = acc[mt][nt][2] + bx, v11 = acc[mt][nt][3] + by;
            if (MODE == 3) { v00 *= 0.125f; v01 *= 0.125f; v10 *= 0.125f; v11 *= 0.125f; }
            if (MODE == 0) {
                float* C = (float*)Cv;
                *(float2*)(C + (size_t)r * N + c) = make_float2(v00, v01);
                *(float2*)(C + (size_t)(r + 8) * N + c) = make_float2(v10, v11);
            } else if (MODE == 1 || MODE == 3) {
                __half* C = (__half*)Cv;
                const int cp = (c & ~15) + perm16(c & 15);
                *(__half2*)(C + (size_t)r * N + cp) = __floats2half2_rn(v00, v01);
                *(__half2*)(C + (size_t)(r + 8) * N + cp) = __floats2half2_rn(v10, v11);
            } else {
                __half* C = (__half*)Cv;
                *(__half2*)(C + (size_t)r * N + c) = __floats2half2_rn(v00, v01);
                *(__half2*)(C + (size_t)(r + 8) * N + c) = __floats2half2_rn(v10, v11);
            }
        }
    }
}

// ===========================================================================
// fp16 flash attention, fully pipelined (unchanged from R14 WIN).
// Q fp16 perm16 pre-scaled; K fp16 perm16; Vt fp16 [b][h][e][s_perm].
// cp.async double-buffered K/Vt tiles. Output fp16 perm16.
// Grid (L/64, H, B), 128 threads (4 warps, 16 q-rows each).
// ===========================================================================
#define AST 80                                  // halves; 160B stride, conflict-free
#define ATTN_TILE (64 * AST)                    // 5120 halves per operand tile
#define ATTN_STAGE (2 * ATTN_TILE)              // K + V
#define ATTN_SMEM ((2 * ATTN_STAGE + ATTN_TILE) * 2)   // 51200 bytes

__global__ __launch_bounds__(128) void attn_tc(
    const __half* __restrict__ Q, const __half* __restrict__ K,
    const __half* __restrict__ Vt, __half* __restrict__ O)
{
    extern __shared__ __half smh[];
    const uint32_t smem_base = smem_u32(smh);
    __half* Ps = smh + 2 * ATTN_STAGE;      // [64 q][AST]; also Q staging

    const int tid  = threadIdx.x;
    const int wid  = tid >> 5;
    const int lane = tid & 31;
    const int gid  = lane >> 2;
    const int tig  = lane & 3;
    const int q0 = blockIdx.x * 64;
    const int h  = blockIdx.y;
    const int b  = blockIdx.z;

    const __half* Qg  = Q + ((size_t)b * Lq + q0) * DHK + h * DK;
    const __half* Kg  = K + ((size_t)b * Sk) * DHK + h * DK;
    const __half* Vtg = Vt + ((size_t)b * NH + h) * DK * Sk;

    // Stage Q through Ps region, extract register fragments (pre-scaled, perm16)
    for (int g = tid; g < 512; g += 128) {
        const int r = g >> 3, c8 = g & 7;
        *(uint4*)&Ps[r * AST + c8 * 8] = *(const uint4*)(Qg + (size_t)r * DHK + c8 * 8);
    }
    __syncthreads();
    const int r0 = wid * 16 + gid;
    uint32_t qf[4][4];
#pragma unroll
    for (int ks = 0; ks < 4; ks++) {
        const uint2 lo = *(const uint2*)(Ps + r0 * AST + ks * 16 + tig * 4);
        const uint2 hi = *(const uint2*)(Ps + (r0 + 8) * AST + ks * 16 + tig * 4);
        qf[ks][0] = lo.x; qf[ks][1] = hi.x;
        qf[ks][2] = lo.y; qf[ks][3] = hi.y;
    }

    // cp.async tile loader: K rows = s, Vt rows = e; both 64 x 128B
    auto issue_tile = [&](int t, int buf) {
        const uint32_t sb = smem_base + (uint32_t)(buf * ATTN_STAGE * 2);
        const uint32_t sv = sb + ATTN_TILE * 2;
#pragma unroll
        for (int u = 0; u < 4; u++) {
            const int g = tid + u * 128;
            const int r = g >> 3, c8 = g & 7;
            cp16(sb + (uint32_t)(r * AST * 2 + c8 * 16),
                 Kg + (size_t)(t * 64 + r) * DHK + c8 * 8);
        }
#pragma unroll
        for (int u = 0; u < 4; u++) {
            const int g = tid + u * 128;
            const int r = g >> 3, c8 = g & 7;
            cp16(sv + (uint32_t)(r * AST * 2 + c8 * 16),
                 Vtg + (size_t)r * Sk + t * 64 + c8 * 8);
        }
        CP_COMMIT();
    };

    float m0 = -INFINITY, m1 = -INFINITY, l0 = 0.f, l1 = 0.f;
    float acc[8][4];
#pragma unroll
    for (int nt = 0; nt < 8; nt++)
#pragma unroll
        for (int r = 0; r < 4; r++) acc[nt][r] = 0.f;

    issue_tile(0, 0);
    for (int t = 0; t < Sk / 64; t++) {
        CP_WAIT0();
        __syncthreads();                     // tile t visible; prior compute done
        if (t + 1 < Sk / 64) issue_tile(t + 1, (t + 1) & 1);

        const __half* Ks = smh + (t & 1) * ATTN_STAGE;
        const __half* Vs = Ks + ATTN_TILE;

        // Scores: QK^T (Q pre-scaled)
        float sc[8][4];
#pragma unroll
        for (int nt = 0; nt < 8; nt++)
#pragma unroll
            for (int r = 0; r < 4; r++) sc[nt][r] = 0.f;
#pragma unroll
        for (int ks = 0; ks < 4; ks++) {
#pragma unroll
            for (int nt = 0; nt < 8; nt++) {
                const uint2 bk = *(const uint2*)(Ks + (nt * 8 + gid) * AST + ks * 16 + tig * 4);
                uint32_t bf[2] = {bk.x, bk.y};
                mma_f16(sc[nt], qf[ks], bf);
            }
        }

        // Online softmax (rows r0, r0+8; spread over 4 tig lanes)
        float mx0 = -INFINITY, mx1 = -INFINITY;
#pragma unroll
        for (int nt = 0; nt < 8; nt++) {
            mx0 = fmaxf(mx0, fmaxf(sc[nt][0], sc[nt][1]));
            mx1 = fmaxf(mx1, fmaxf(sc[nt][2], sc[nt][3]));
        }
        mx0 = fmaxf(mx0, __shfl_xor_sync(0xffffffffu, mx0, 1));
        mx0 = fmaxf(mx0, __shfl_xor_sync(0xffffffffu, mx0, 2));
        mx1 = fmaxf(mx1, __shfl_xor_sync(0xffffffffu, mx1, 1));
        mx1 = fmaxf(mx1, __shfl_xor_sync(0xffffffffu, mx1, 2));
        const float mn0 = fmaxf(m0, mx0), mn1 = fmaxf(m1, mx1);
        const float f0 = __expf(m0 - mn0), f1 = __expf(m1 - mn1);
        float sum0 = 0.f, sum1 = 0.f;
#pragma unroll
        for (int nt = 0; nt < 8; nt++) {
            sc[nt][0] = __expf(sc[nt][0] - mn0);
            sc[nt][1] = __expf(sc[nt][1] - mn0);
            sc[nt][2] = __expf(sc[nt][2] - mn1);
            sc[nt][3] = __expf(sc[nt][3] - mn1);
            sum0 += sc[nt][0] + sc[nt][1];
            sum1 += sc[nt][2] + sc[nt][3];
        }
        sum0 += __shfl_xor_sync(0xffffffffu, sum0, 1);
        sum0 += __shfl_xor_sync(0xffffffffu, sum0, 2);
        sum1 += __shfl_xor_sync(0xffffffffu, sum1, 1);
        sum1 += __shfl_xor_sync(0xffffffffu, sum1, 2);
        l0 = l0 * f0 + sum0;  m0 = mn0;
        l1 = l1 * f1 + sum1;  m1 = mn1;

#pragma unroll
        for (int nt = 0; nt < 8; nt++) {
            acc[nt][0] *= f0; acc[nt][1] *= f0;
            acc[nt][2] *= f1; acc[nt][3] *= f1;
        }

        // P -> fp16 perm16 (cols = s), warp-private rows of Ps
#pragma unroll
        for (int nt = 0; nt < 8; nt++) {
            const int c = nt * 8 + tig * 2;
            const int cp = (c & ~15) + perm16(c & 15);
            *(__half2*)&Ps[r0 * AST + cp] = __floats2half2_rn(sc[nt][0], sc[nt][1]);
            *(__half2*)&Ps[(r0 + 8) * AST + cp] = __floats2half2_rn(sc[nt][2], sc[nt][3]);
        }
        __syncwarp();

        // PV: acc[e-tile] += P[q][s] @ Vt[e][s]
#pragma unroll
        for (int ks = 0; ks < 4; ks++) {
            const uint2 lo = *(const uint2*)(Ps + r0 * AST + ks * 16 + tig * 4);
            const uint2 hi = *(const uint2*)(Ps + (r0 + 8) * AST + ks * 16 + tig * 4);
            uint32_t af[4] = {lo.x, hi.x, lo.y, hi.y};
#pragma unroll
            for (int nt = 0; nt < 8; nt++) {
                const uint2 bv = *(const uint2*)(Vs + (nt * 8 + gid) * AST + ks * 16 + tig * 4);
                uint32_t bf[2] = {bv.x, bv.y};
                mma_f16(acc[nt], af, bf);
            }
        }
    }

    // Epilogue: normalize, fp16 + perm16 store (feeds out-proj A operand)
    const float inv0 = 1.f / l0, inv1 = 1.f / l1;
    __half* Og = O + ((size_t)b * Lq + q0 + r0) * DHK + h * DK;
#pragma unroll
    for (int nt = 0; nt < 8; nt++) {
        const int c = nt * 8 + tig * 2;
        const int cp = (c & ~15) + perm16(c & 15);
        *(__half2*)(Og + cp) = __floats2half2_rn(acc[nt][0] * inv0, acc[nt][1] * inv0);
        *(__half2*)(Og + (size_t)8 * DHK + cp) =
            __floats2half2_rn(acc[nt][2] * inv1, acc[nt][3] * inv1);
    }
}

// ===========================================================================
// Launch.  Order chosen so ncu's capture slot (#5, 0-indexed) lands on the
// K-proj GEMM (K=4096 shape, not yet profiled):
//   0 round_perm_fused, 1 transpose_all, 2 gemmQ, 3 gemmV, 4 vtrans,
//   5 gemmK, 6 attn, 7 gemmOut
// (gemmK only needs to precede attn — ordering is legal.)
// ===========================================================================
extern "C" void kernel_launch(void* const* d_in, const int* in_sizes, int n_in,
                              void* d_out, int out_size)
{
    const float* target = (const float*)d_in[0];
    const float* source = (const float*)d_in[1];
    const float* Wq = (const float*)d_in[2];
    const float* bq = (const float*)d_in[3];
    const float* Wk = (const float*)d_in[4];
    const float* bk = (const float*)d_in[5];
    const float* Wv = (const float*)d_in[6];
    const float* bv = (const float*)d_in[7];
    const float* Wo = (const float*)d_in[8];
    const float* bo = (const float*)d_in[9];
    float* out = (float*)d_out;

    __half* Qh; cudaGetSymbolAddress((void**)&Qh, g_Qh);
    __half* Kh; cudaGetSymbolAddress((void**)&Kh, g_Kh);
    __half* Vh; cudaGetSymbolAddress((void**)&Vh, g_Vh);
    __half* Vtb; cudaGetSymbolAddress((void**)&Vtb, g_Vt);
    __half* Hb; cudaGetSymbolAddress((void**)&Hb, g_H);
    __half* Sr; cudaGetSymbolAddress((void**)&Sr, g_Sr);
    __half* WTq; cudaGetSymbolAddress((void**)&WTq, g_WTq);
    __half* WTk; cudaGetSymbolAddress((void**)&WTk, g_WTk);
    __half* WTv; cudaGetSymbolAddress((void**)&WTv, g_WTv);
    __half* WTo; cudaGetSymbolAddress((void**)&WTo, g_WTo);

    const int ML = Bz * Lq;   // 16384
    const int MS = Bz * Sk;   // 8192

    cudaFuncSetAttribute(gemm_mma<0>, cudaFuncAttributeMaxDynamicSharedMemorySize, SMEM_GEMM);
    cudaFuncSetAttribute(gemm_mma<1>, cudaFuncAttributeMaxDynamicSharedMemorySize, SMEM_GEMM);
    cudaFuncSetAttribute(gemm_mma<2>, cudaFuncAttributeMaxDynamicSharedMemorySize, SMEM_GEMM);
    cudaFuncSetAttribute(gemm_mma<3>, cudaFuncAttributeMaxDynamicSharedMemorySize, SMEM_GEMM);
    cudaFuncSetAttribute(attn_tc, cudaFuncAttributeMaxDynamicSharedMemorySize, ATTN_SMEM);

    // 0: fp16 + perm16 both inputs in one launch
    const int nt4 = ML * DM / 4;        // 4M
    const int ns4 = MS * DLLM / 4;      // 8M
    round_perm_fused<<<(nt4 + ns4) / 256, 256>>>(
        (const float4*)target, Hb, nt4, (const float4*)source, Sr, ns4);

    // 1: all four weight transposes in one launch
    transpose_all<<<TRANS_TILES, 256>>>(Wq, Wk, Wv, Wo, WTq, WTk, WTv, WTo);

    // 2: Q = h(target) @ Wq + bq  -> fp16 perm16 scaled by 0.125
    gemm_mma<3><<<dim3(DHK / GN, ML / GM), 128, SMEM_GEMM>>>(Hb, WTq, bq, Qh, DM, DHK);

    // 3: V = h(source) @ Wv + bv  -> fp16 natural
    gemm_mma<2><<<dim3(DHK / GN, MS / GM), 128, SMEM_GEMM>>>(Sr, WTv, bv, Vh, DLLM, DHK);

    // 4: V pre-transpose for PV
    vtrans<<<dim3(Sk / 64, NH, Bz), 128>>>(Vh, Vtb);

    // 5: K = h(source) @ Wk + bk  -> fp16 perm16   (ncu capture slot)
    gemm_mma<1><<<dim3(DHK / GN, MS / GM), 128, SMEM_GEMM>>>(Sr, WTk, bk, Kh, DLLM, DHK);

    // 6: Attention (writes fp16+perm16 into Hb — safe: Q-proj, the only
    //    reader of Hb's previous contents, already ran)
    attn_tc<<<dim3(Lq / 64, NH, Bz), 128, ATTN_SMEM>>>(Qh, Kh, Vtb, Hb);

    // 7: out = attn @ Wo + bo  (final output fp32)
    gemm_mma<0><<<dim3(DLLM / GN, ML / GM), 128, SMEM_GEMM>>>(Hb, WTo, bo, out, DHK, DLLM);
}